// round 8
// baseline (speedup 1.0000x reference)
#include <cuda_runtime.h>
#include <cuda_bf16.h>
#include <math.h>
#include <stdint.h>

// Problem constants
#define B_  2
#define S_  2048
#define H_  4096
#define NH_ 32
#define NKV_ 8
#define HD_ 128
#define M_  (B_ * S_)          // 4096 rows
#define QN_ (NH_ * HD_)        // 4096
#define KN_ (NKV_ * HD_)       // 1024
#define QKV_N (QN_ + 2 * KN_)  // 6144

// Scratch (device globals; no allocations allowed)
__device__ float g_Xr[M_ * H_];          // pre-rounded X
__device__ float g_Wqkv[H_ * QKV_N];     // concat pre-rounded [H][6144]
__device__ float g_bqkv[QKV_N];
__device__ float g_QKV[M_ * QKV_N];      // fused projection output
__device__ float g_Wo[QN_ * H_];         // pre-rounded Wo
__device__ float g_AO[M_ * QN_];
__device__ __nv_bfloat16 g_Khi[M_ * KN_], g_Klo[M_ * KN_];
__device__ __nv_bfloat16 g_Vhi[M_ * KN_], g_Vlo[M_ * KN_];

__device__ __forceinline__ float round_tf32_f(float f) {
    unsigned r;
    asm("cvt.rna.tf32.f32 %0, %1;" : "=r"(r) : "f"(f));
    return __uint_as_float(r);
}

__device__ __forceinline__ void split2(float x, float y, unsigned& hi, unsigned& lo)
{
    __nv_bfloat162 h = __floats2bfloat162_rn(x, y);
    float hx = __bfloat162float(h.x), hy = __bfloat162float(h.y);
    __nv_bfloat162 l = __floats2bfloat162_rn(x - hx, y - hy);
    hi = *(unsigned*)&h;
    lo = *(unsigned*)&l;
}

// ---------------------------------------------------------------------------
// Fused prep: one grid-stride kernel over segmented float4 index space.
// seg0: Xr = rnd(X); seg1: Wqkv = rnd(concat Wq|Wk|Wv); seg2: Wor = rnd(Wo);
// seg3: bqkv = concat(bq,bk,bv).
// ---------------------------------------------------------------------------
#define SEG0 (M_ * H_ / 4)
#define SEG1 (H_ * QKV_N / 4)
#define SEG2 (QN_ * H_ / 4)
#define SEG3 (QKV_N / 4)
#define SEG_TOTAL (SEG0 + SEG1 + SEG2 + SEG3)

__device__ __forceinline__ float4 rnd4(float4 v) {
    v.x = round_tf32_f(v.x);
    v.y = round_tf32_f(v.y);
    v.z = round_tf32_f(v.z);
    v.w = round_tf32_f(v.w);
    return v;
}

__global__ __launch_bounds__(256)
void prep_all(const float* __restrict__ X,
              const float* __restrict__ Wq, const float* __restrict__ Wk,
              const float* __restrict__ Wv, const float* __restrict__ Wo,
              const float* __restrict__ bq, const float* __restrict__ bk,
              const float* __restrict__ bv,
              float* __restrict__ Xr, float* __restrict__ Wqkv,
              float* __restrict__ Wor, float* __restrict__ bqkv)
{
    const int stride = gridDim.x * 256;
    for (int u = blockIdx.x * 256 + threadIdx.x; u < SEG_TOTAL; u += stride) {
        if (u < SEG0) {
            *(float4*)(Xr + u * 4) = rnd4(*(const float4*)(X + (size_t)u * 4));
        } else if (u < SEG0 + SEG1) {
            const int j = u - SEG0;                  // float4 idx in [H][6144/4]
            const int row = j / (QKV_N / 4);
            const int c4  = j - row * (QKV_N / 4);
            const int c = c4 * 4;
            float4 v;
            if (c < QN_)
                v = *(const float4*)(Wq + (size_t)row * QN_ + c);
            else if (c < QN_ + KN_)
                v = *(const float4*)(Wk + (size_t)row * KN_ + (c - QN_));
            else
                v = *(const float4*)(Wv + (size_t)row * KN_ + (c - QN_ - KN_));
            *(float4*)(Wqkv + (size_t)row * QKV_N + c) = rnd4(v);
        } else if (u < SEG0 + SEG1 + SEG2) {
            const int j = u - SEG0 - SEG1;
            *(float4*)(Wor + (size_t)j * 4) = rnd4(*(const float4*)(Wo + (size_t)j * 4));
        } else {
            const int j = u - SEG0 - SEG1 - SEG2;
            const int c = j * 4;
            float4 v;
            if (c < QN_)            v = *(const float4*)(bq + c);
            else if (c < QN_ + KN_) v = *(const float4*)(bk + c - QN_);
            else                    v = *(const float4*)(bv + c - QN_ - KN_);
            *(float4*)(bqkv + c) = v;
        }
    }
}

// ---------------------------------------------------------------------------
// TF32 tensor-core GEMM v2: 128x256 CTA tile, 256 threads (8 warps, 64x64
// warp tiles), BK=16, 3-stage cp.async pipeline in dynamic smem.
// Inputs pre-rounded to tf32 grid -> raw-bit MMA (bit-identical accumulation
// order to the 128x128 version).
// ---------------------------------------------------------------------------
#define G2_BM 128
#define G2_BN 256
#define G2_AS 20                      // A row stride (16 + 4 pad)
#define G2_BS 264                     // B row stride (256 + 8 pad)
#define G2_STG (G2_BM * G2_AS + 16 * G2_BS)   // 2560 + 4224 = 6784 floats
#define G2_SMEM (3 * G2_STG * 4)              // 81408 bytes

__device__ __forceinline__ void mma_tf32(float& d0, float& d1, float& d2, float& d3,
                                         unsigned a0, unsigned a1, unsigned a2, unsigned a3,
                                         unsigned b0, unsigned b1)
{
    asm volatile(
        "mma.sync.aligned.m16n8k8.row.col.f32.tf32.tf32.f32 "
        "{%0,%1,%2,%3}, {%4,%5,%6,%7}, {%8,%9}, {%0,%1,%2,%3};"
        : "+f"(d0), "+f"(d1), "+f"(d2), "+f"(d3)
        : "r"(a0), "r"(a1), "r"(a2), "r"(a3), "r"(b0), "r"(b1));
}

__device__ __forceinline__ void cp_async16(void* smem_dst, const void* gsrc) {
    unsigned dst = (unsigned)__cvta_generic_to_shared(smem_dst);
    asm volatile("cp.async.cg.shared.global [%0], [%1], 16;" :: "r"(dst), "l"(gsrc));
}

__global__ __launch_bounds__(256)
void gemm_tf32(const float* __restrict__ A, const float* __restrict__ B,
               const float* __restrict__ bias, float* __restrict__ C,
               int M, int N, int K)
{
    extern __shared__ float smem2[];

    const int tid  = threadIdx.x;
    const int wid  = tid >> 5;
    const int lane = tid & 31;
    const int warp_m = (wid & 1) * 64;   // 2 warps along M
    const int warp_n = (wid >> 1) * 64;  // 4 warps along N
    const int brow = blockIdx.y * G2_BM;
    const int bcol = blockIdx.x * G2_BN;
    const int lr = lane >> 2;
    const int lc = lane & 3;

    float acc[4][8][4];
#pragma unroll
    for (int mt = 0; mt < 4; mt++)
#pragma unroll
        for (int nt = 0; nt < 8; nt++)
#pragma unroll
            for (int i = 0; i < 4; i++) acc[mt][nt][i] = 0.f;

    auto load_stage = [&](int s, int k0) {
        float* As = smem2 + s * G2_STG;
        float* Bs = As + G2_BM * G2_AS;
#pragma unroll
        for (int it = 0; it < 2; it++) {
            const int id = tid + 256 * it;          // 0..511
            const int r = id >> 2, c = (id & 3) * 4;
            cp_async16(&As[r * G2_AS + c], &A[(size_t)(brow + r) * K + k0 + c]);
        }
#pragma unroll
        for (int it = 0; it < 4; it++) {
            const int id = tid + 256 * it;          // 0..1023
            const int r = id >> 6, c = (id & 63) * 4;
            cp_async16(&Bs[r * G2_BS + c], &B[(size_t)(k0 + r) * N + bcol + c]);
        }
        asm volatile("cp.async.commit_group;");
    };

    const int KT = K / 16;
    load_stage(0, 0);
    load_stage(1, 16);

    for (int kt = 0; kt < KT; kt++) {
        const int s = kt % 3;
        if (kt + 1 < KT) asm volatile("cp.async.wait_group 1;");
        else             asm volatile("cp.async.wait_group 0;");
        __syncthreads();

        if (kt + 2 < KT) load_stage((kt + 2) % 3, (kt + 2) * 16);

        const float* As = smem2 + s * G2_STG;
        const float* Bs = As + G2_BM * G2_AS;

#pragma unroll
        for (int ks = 0; ks < 2; ks++) {
            const int k0 = ks * 8;
            unsigned af[4][4], bf[8][2];
#pragma unroll
            for (int mt = 0; mt < 4; mt++) {
                const float* ap = As + (warp_m + mt * 16 + lr) * G2_AS + k0 + lc;
                af[mt][0] = __float_as_uint(ap[0]);
                af[mt][1] = __float_as_uint(ap[8 * G2_AS]);
                af[mt][2] = __float_as_uint(ap[4]);
                af[mt][3] = __float_as_uint(ap[8 * G2_AS + 4]);
            }
#pragma unroll
            for (int nt = 0; nt < 8; nt++) {
                const float* bp = Bs + (k0 + lc) * G2_BS + warp_n + nt * 8 + lr;
                bf[nt][0] = __float_as_uint(bp[0]);
                bf[nt][1] = __float_as_uint(bp[4 * G2_BS]);
            }
#pragma unroll
            for (int mt = 0; mt < 4; mt++)
#pragma unroll
                for (int nt = 0; nt < 8; nt++)
                    mma_tf32(acc[mt][nt][0], acc[mt][nt][1], acc[mt][nt][2], acc[mt][nt][3],
                             af[mt][0], af[mt][1], af[mt][2], af[mt][3],
                             bf[nt][0], bf[nt][1]);
        }
    }

#pragma unroll
    for (int mt = 0; mt < 4; mt++) {
#pragma unroll
        for (int nt = 0; nt < 8; nt++) {
            const int row0 = brow + warp_m + mt * 16 + lr;
            const int col  = bcol + warp_n + nt * 8 + lc * 2;
            const float b0 = bias ? bias[col]     : 0.f;
            const float b1 = bias ? bias[col + 1] : 0.f;
            float2 v0 = make_float2(acc[mt][nt][0] + b0, acc[mt][nt][1] + b1);
            float2 v1 = make_float2(acc[mt][nt][2] + b0, acc[mt][nt][3] + b1);
            *(float2*)&C[(size_t)row0 * N + col]       = v0;
            *(float2*)&C[(size_t)(row0 + 8) * N + col] = v1;
        }
    }
}

// ---------------------------------------------------------------------------
// RoPE over fused QKV (unchanged from R7)
// ---------------------------------------------------------------------------
__global__ __launch_bounds__(128)
void rope48_kernel(float* __restrict__ QKV,
                   __nv_bfloat16* __restrict__ Khi, __nv_bfloat16* __restrict__ Klo,
                   __nv_bfloat16* __restrict__ Vhi, __nv_bfloat16* __restrict__ Vlo,
                   const int* __restrict__ pos_ids)
{
    const int row  = blockIdx.x;
    const int head = blockIdx.y;
    const int d    = threadIdx.x;

    if (head >= NH_ + NKV_) {
        const int kvh = head - NH_ - NKV_;
        const float v = QKV[(size_t)row * QKV_N + QN_ + KN_ + kvh * HD_ + d];
        const __nv_bfloat16 h = __float2bfloat16(v);
        const size_t off = (size_t)row * KN_ + kvh * HD_;
        Vhi[off + d] = h;
        Vlo[off + d] = __float2bfloat16(v - __bfloat162float(h));
        return;
    }

    const int pos = pos_ids[row];
    const int i = d & 63;
    const float inv_freq = exp2f(-(float)(2 * i) * (1.0f / 128.0f) * 13.28771238f);
    const float ang = (float)pos * inv_freq;
    float c, s;
    sincosf(ang, &s, &c);

    if (head < NH_) {
        float* base = QKV + (size_t)row * QKV_N + head * HD_;
        const float x = base[d];
        const float other = (d < 64) ? -base[d + 64] : base[d - 64];
        const float v = (x * c + other * s) * 0.08838834764831845f;
        __syncthreads();
        base[d] = v;
    } else {
        const int kvh = head - NH_;
        const float* base = QKV + (size_t)row * QKV_N + QN_ + kvh * HD_;
        const float x = base[d];
        const float other = (d < 64) ? -base[d + 64] : base[d - 64];
        const float v = x * c + other * s;
        const __nv_bfloat16 h = __float2bfloat16(v);
        const size_t off = (size_t)row * KN_ + kvh * HD_;
        Khi[off + d] = h;
        Klo[off + d] = __float2bfloat16(v - __bfloat162float(h));
    }
}

// ---------------------------------------------------------------------------
// Tensor-core flash attention, bf16x3 (unchanged from R7)
// ---------------------------------------------------------------------------
#define BQ 64
#define BK 64
#define KSTR 136
#define ABUF (BK * KSTR * 2)
#define ATT_SMEM (4 * ABUF)

__device__ __forceinline__ void mma_bf16(float c[4], const unsigned a[4],
                                         unsigned b0, unsigned b1)
{
    asm volatile(
        "mma.sync.aligned.m16n8k16.row.col.f32.bf16.bf16.f32 "
        "{%0,%1,%2,%3}, {%4,%5,%6,%7}, {%8,%9}, {%0,%1,%2,%3};"
        : "+f"(c[0]), "+f"(c[1]), "+f"(c[2]), "+f"(c[3])
        : "r"(a[0]), "r"(a[1]), "r"(a[2]), "r"(a[3]), "r"(b0), "r"(b1));
}

__device__ __forceinline__ void ldsm4(unsigned r[4], const void* p)
{
    unsigned a = (unsigned)__cvta_generic_to_shared(p);
    asm volatile(
        "ldmatrix.sync.aligned.m8n8.x4.shared.b16 {%0,%1,%2,%3}, [%4];"
        : "=r"(r[0]), "=r"(r[1]), "=r"(r[2]), "=r"(r[3]) : "r"(a));
}

__device__ __forceinline__ void ldsm4t(unsigned r[4], const void* p)
{
    unsigned a = (unsigned)__cvta_generic_to_shared(p);
    asm volatile(
        "ldmatrix.sync.aligned.m8n8.x4.trans.shared.b16 {%0,%1,%2,%3}, [%4];"
        : "=r"(r[0]), "=r"(r[1]), "=r"(r[2]), "=r"(r[3]) : "r"(a));
}

__global__ __launch_bounds__(128)
void attn_mma(const float* __restrict__ QKV,
              const __nv_bfloat16* __restrict__ Khi, const __nv_bfloat16* __restrict__ Klo,
              const __nv_bfloat16* __restrict__ Vhi, const __nv_bfloat16* __restrict__ Vlo,
              float* __restrict__ AO)
{
    extern __shared__ char smraw[];
    __nv_bfloat16* sKhi = (__nv_bfloat16*)(smraw);
    __nv_bfloat16* sKlo = (__nv_bfloat16*)(smraw + ABUF);
    __nv_bfloat16* sVhi = (__nv_bfloat16*)(smraw + 2 * ABUF);
    __nv_bfloat16* sVlo = (__nv_bfloat16*)(smraw + 3 * ABUF);

    const int qt = blockIdx.x, h = blockIdx.y, b = blockIdx.z;
    const int q0 = qt * BQ;
    const int kvh = h >> 2;
    const int tid = threadIdx.x;
    const int w = tid >> 5, lane = tid & 31;
    const int lr = lane >> 2, lc = lane & 3;

    const int qrow0 = q0 + w * 16 + lr;
    const int qrow1 = qrow0 + 8;

    unsigned qa_hi[8][4], qa_lo[8][4];
    {
        const float* Q0 = QKV + ((size_t)(b * S_) + qrow0) * QKV_N + h * HD_;
        const float* Q1 = QKV + ((size_t)(b * S_) + qrow1) * QKV_N + h * HD_;
#pragma unroll
        for (int kt = 0; kt < 8; kt++) {
            float2 v;
            v = *(const float2*)(Q0 + kt * 16 + 2 * lc);
            split2(v.x, v.y, qa_hi[kt][0], qa_lo[kt][0]);
            v = *(const float2*)(Q1 + kt * 16 + 2 * lc);
            split2(v.x, v.y, qa_hi[kt][1], qa_lo[kt][1]);
            v = *(const float2*)(Q0 + kt * 16 + 2 * lc + 8);
            split2(v.x, v.y, qa_hi[kt][2], qa_lo[kt][2]);
            v = *(const float2*)(Q1 + kt * 16 + 2 * lc + 8);
            split2(v.x, v.y, qa_hi[kt][3], qa_lo[kt][3]);
        }
    }

    float m0 = -1e30f, m1 = -1e30f, l0 = 0.f, l1 = 0.f;
    float o[16][4];
#pragma unroll
    for (int i = 0; i < 16; i++)
#pragma unroll
        for (int j = 0; j < 4; j++) o[i][j] = 0.f;

    const int nTiles = qt + 1;
    const int wEnd = q0 + w * 16 + 16;
    const int ldr = (lane & 7) + ((lane >> 3) & 1) * 8;
    const int ldc = ((lane >> 4) & 1) * 8;
    const int klr = lane & 7;
    const int kmg = lane >> 3;

    const size_t kv_base = (size_t)(b * S_) * KN_ + kvh * HD_;

    auto load_pair = [&](__nv_bfloat16* dhi, __nv_bfloat16* dlo,
                         const __nv_bfloat16* ghi, const __nv_bfloat16* glo, int kbase) {
        const size_t off = kv_base + (size_t)kbase * KN_;
#pragma unroll
        for (int j = 0; j < 8; j++) {
            const int idx = tid + 128 * j;
            const int row = idx >> 4, c16 = idx & 15;
            const size_t g = off + (size_t)row * KN_ + c16 * 8;
            cp_async16(dhi + row * KSTR + c16 * 8, ghi + g);
            cp_async16(dlo + row * KSTR + c16 * 8, glo + g);
        }
        asm volatile("cp.async.commit_group;");
    };

    load_pair(sKhi, sKlo, Khi, Klo, 0);
    asm volatile("cp.async.wait_group 0;");
    __syncthreads();

    for (int kt = 0; kt < nTiles; kt++) {
        const int kbase = kt * BK;
        const bool active = kbase < wEnd;

        load_pair(sVhi, sVlo, Vhi, Vlo, kbase);

        float sA[8][4];
        unsigned pa_hi[4][4], pa_lo[4][4];

        if (active) {
#pragma unroll
            for (int nt = 0; nt < 8; nt++)
#pragma unroll
                for (int j = 0; j < 4; j++) sA[nt][j] = 0.f;

#pragma unroll
            for (int dkt2 = 0; dkt2 < 4; dkt2++) {
                const int col = dkt2 * 32 + kmg * 8;
#pragma unroll
                for (int nt = 0; nt < 8; nt++) {
                    unsigned bh[4], bl[4];
                    ldsm4(bh, sKhi + (nt * 8 + klr) * KSTR + col);
                    ldsm4(bl, sKlo + (nt * 8 + klr) * KSTR + col);
                    mma_bf16(sA[nt], qa_hi[2 * dkt2],     bh[0], bh[1]);
                    mma_bf16(sA[nt], qa_hi[2 * dkt2],     bl[0], bl[1]);
                    mma_bf16(sA[nt], qa_lo[2 * dkt2],     bh[0], bh[1]);
                    mma_bf16(sA[nt], qa_hi[2 * dkt2 + 1], bh[2], bh[3]);
                    mma_bf16(sA[nt], qa_hi[2 * dkt2 + 1], bl[2], bl[3]);
                    mma_bf16(sA[nt], qa_lo[2 * dkt2 + 1], bh[2], bh[3]);
                }
            }

            if (kbase + BK > qrow0) {
#pragma unroll
                for (int nt = 0; nt < 8; nt++) {
                    const int j0 = kbase + nt * 8 + 2 * lc;
                    if (j0 > qrow0)     sA[nt][0] = -1e30f;
                    if (j0 + 1 > qrow0) sA[nt][1] = -1e30f;
                    if (j0 > qrow1)     sA[nt][2] = -1e30f;
                    if (j0 + 1 > qrow1) sA[nt][3] = -1e30f;
                }
            }

            float mt0 = -1e30f, mt1 = -1e30f;
#pragma unroll
            for (int nt = 0; nt < 8; nt++) {
                mt0 = fmaxf(mt0, fmaxf(sA[nt][0], sA[nt][1]));
                mt1 = fmaxf(mt1, fmaxf(sA[nt][2], sA[nt][3]));
            }
            mt0 = fmaxf(mt0, __shfl_xor_sync(0xffffffffu, mt0, 1));
            mt0 = fmaxf(mt0, __shfl_xor_sync(0xffffffffu, mt0, 2));
            mt1 = fmaxf(mt1, __shfl_xor_sync(0xffffffffu, mt1, 1));
            mt1 = fmaxf(mt1, __shfl_xor_sync(0xffffffffu, mt1, 2));

            const float nm0 = fmaxf(m0, mt0);
            const float nm1 = fmaxf(m1, mt1);
            const float al0 = __expf(m0 - nm0);
            const float al1 = __expf(m1 - nm1);

            float rs0 = 0.f, rs1 = 0.f;
#pragma unroll
            for (int nt = 0; nt < 8; nt++) {
                sA[nt][0] = __expf(sA[nt][0] - nm0);
                sA[nt][1] = __expf(sA[nt][1] - nm0);
                sA[nt][2] = __expf(sA[nt][2] - nm1);
                sA[nt][3] = __expf(sA[nt][3] - nm1);
                rs0 += sA[nt][0] + sA[nt][1];
                rs1 += sA[nt][2] + sA[nt][3];
            }
            rs0 += __shfl_xor_sync(0xffffffffu, rs0, 1);
            rs0 += __shfl_xor_sync(0xffffffffu, rs0, 2);
            rs1 += __shfl_xor_sync(0xffffffffu, rs1, 1);
            rs1 += __shfl_xor_sync(0xffffffffu, rs1, 2);

            l0 = l0 * al0 + rs0;
            l1 = l1 * al1 + rs1;
            m0 = nm0; m1 = nm1;

#pragma unroll
            for (int i = 0; i < 16; i++) {
                o[i][0] *= al0; o[i][1] *= al0;
                o[i][2] *= al1; o[i][3] *= al1;
            }

#pragma unroll
            for (int t = 0; t < 4; t++) {
                split2(sA[2 * t][0],     sA[2 * t][1],     pa_hi[t][0], pa_lo[t][0]);
                split2(sA[2 * t][2],     sA[2 * t][3],     pa_hi[t][1], pa_lo[t][1]);
                split2(sA[2 * t + 1][0], sA[2 * t + 1][1], pa_hi[t][2], pa_lo[t][2]);
                split2(sA[2 * t + 1][2], sA[2 * t + 1][3], pa_hi[t][3], pa_lo[t][3]);
            }
        }

        asm volatile("cp.async.wait_group 0;");
        __syncthreads();

        if (kt + 1 < nTiles) load_pair(sKhi, sKlo, Khi, Klo, kbase + BK);

        if (active) {
#pragma unroll
            for (int t = 0; t < 4; t++) {
#pragma unroll
                for (int np = 0; np < 8; np++) {
                    unsigned vh[4], vl[4];
                    ldsm4t(vh, sVhi + (t * 16 + ldr) * KSTR + np * 16 + ldc);
                    ldsm4t(vl, sVlo + (t * 16 + ldr) * KSTR + np * 16 + ldc);
                    mma_bf16(o[2 * np],     pa_hi[t], vh[0], vh[1]);
                    mma_bf16(o[2 * np],     pa_hi[t], vl[0], vl[1]);
                    mma_bf16(o[2 * np],     pa_lo[t], vh[0], vh[1]);
                    mma_bf16(o[2 * np + 1], pa_hi[t], vh[2], vh[3]);
                    mma_bf16(o[2 * np + 1], pa_hi[t], vl[2], vl[3]);
                    mma_bf16(o[2 * np + 1], pa_lo[t], vh[2], vh[3]);
                }
            }
        }

        asm volatile("cp.async.wait_group 0;");
        __syncthreads();
    }

    const float il0 = 1.f / l0;
    const float il1 = 1.f / l1;
    float* O0 = AO + ((size_t)(b * S_) + qrow0) * QN_ + h * HD_;
    float* O1 = AO + ((size_t)(b * S_) + qrow1) * QN_ + h * HD_;
#pragma unroll
    for (int nt = 0; nt < 16; nt++) {
        *(float2*)(O0 + nt * 8 + 2 * lc) =
            make_float2(round_tf32_f(o[nt][0] * il0), round_tf32_f(o[nt][1] * il0));
        *(float2*)(O1 + nt * 8 + 2 * lc) =
            make_float2(round_tf32_f(o[nt][2] * il1), round_tf32_f(o[nt][3] * il1));
    }
}

// ---------------------------------------------------------------------------
// Launcher
// ---------------------------------------------------------------------------
extern "C" void kernel_launch(void* const* d_in, const int* in_sizes, int n_in,
                              void* d_out, int out_size)
{
    const float* X   = (const float*)d_in[0];
    const int*   pos = (const int*)  d_in[1];
    const float* Wq  = (const float*)d_in[2];
    const float* bq  = (const float*)d_in[3];
    const float* Wk  = (const float*)d_in[4];
    const float* bk  = (const float*)d_in[5];
    const float* Wv  = (const float*)d_in[6];
    const float* bv  = (const float*)d_in[7];
    const float* Wo  = (const float*)d_in[8];
    float* out = (float*)d_out;

    float *Xr, *Wqkv, *bqkv, *QKV, *Wor, *AOb;
    __nv_bfloat16 *Khi, *Klo, *Vhi, *Vlo;
    cudaGetSymbolAddress((void**)&Xr,   g_Xr);
    cudaGetSymbolAddress((void**)&Wqkv, g_Wqkv);
    cudaGetSymbolAddress((void**)&bqkv, g_bqkv);
    cudaGetSymbolAddress((void**)&QKV,  g_QKV);
    cudaGetSymbolAddress((void**)&Wor,  g_Wo);
    cudaGetSymbolAddress((void**)&AOb,  g_AO);
    cudaGetSymbolAddress((void**)&Khi,  g_Khi);
    cudaGetSymbolAddress((void**)&Klo,  g_Klo);
    cudaGetSymbolAddress((void**)&Vhi,  g_Vhi);
    cudaGetSymbolAddress((void**)&Vlo,  g_Vlo);

    cudaFuncSetAttribute(attn_mma,  cudaFuncAttributeMaxDynamicSharedMemorySize, ATT_SMEM);
    cudaFuncSetAttribute(gemm_tf32, cudaFuncAttributeMaxDynamicSharedMemorySize, G2_SMEM);

    // Fused prep (pre-round + concat + bias) in one launch
    prep_all<<<1184, 256>>>(X, Wq, Wk, Wv, Wo, bq, bk, bv, Xr, Wqkv, Wor, bqkv);

    // Fused QKV projection: [4096 x 4096] @ [4096 x 6144]
    gemm_tf32<<<dim3(QKV_N / G2_BN, M_ / G2_BM), 256, G2_SMEM>>>(
        Xr, Wqkv, bqkv, QKV, M_, QKV_N, H_);

    // RoPE + K/V split
    rope48_kernel<<<dim3(M_, NH_ + 2 * NKV_), 128>>>(QKV, Khi, Klo, Vhi, Vlo, pos);

    // Attention
    attn_mma<<<dim3(S_ / BQ, NH_, B_), 128, ATT_SMEM>>>(QKV, Khi, Klo, Vhi, Vlo, AOb);

    // Output projection: [4096 x 4096] @ [4096 x 4096]
    gemm_tf32<<<dim3(QN_ / G2_BN, M_ / G2_BM), 256, G2_SMEM>>>(
        AOb, Wor, nullptr, out, M_, QN_, H_);
}

// round 9
// speedup vs baseline: 1.6045x; 1.6045x over previous
#include <cuda_runtime.h>
#include <cuda_bf16.h>
#include <cuda_fp16.h>
#include <math.h>
#include <stdint.h>

// Problem constants
#define B_  2
#define S_  2048
#define H_  4096
#define NH_ 32
#define NKV_ 8
#define HD_ 128
#define M_  (B_ * S_)          // 4096 rows
#define QN_ (NH_ * HD_)        // 4096
#define KN_ (NKV_ * HD_)       // 1024
#define QKV_N (QN_ + 2 * KN_)  // 6144

// Scratch (device globals; no allocations allowed)
__device__ __half g_Xh[M_ * H_];          // fp16-rounded X
__device__ __half g_Wqkvh[H_ * QKV_N];    // concat fp16 weights [H][6144]
__device__ float  g_bqkv[QKV_N];
__device__ float  g_QKV[M_ * QKV_N];      // fused projection output (fp32)
__device__ __half g_Woh[QN_ * H_];        // fp16 Wo
__device__ __half g_AOh[M_ * QN_];        // attention output (fp16)
__device__ __nv_bfloat16 g_Khi[M_ * KN_], g_Klo[M_ * KN_];
__device__ __nv_bfloat16 g_Vhi[M_ * KN_], g_Vlo[M_ * KN_];

__device__ __forceinline__ void split2(float x, float y, unsigned& hi, unsigned& lo)
{
    __nv_bfloat162 h = __floats2bfloat162_rn(x, y);
    float hx = __bfloat162float(h.x), hy = __bfloat162float(h.y);
    __nv_bfloat162 l = __floats2bfloat162_rn(x - hx, y - hy);
    hi = *(unsigned*)&h;
    lo = *(unsigned*)&l;
}

__device__ __forceinline__ void st_half4(__half* p, float4 v)
{
    *(__half2*)(p)     = __floats2half2_rn(v.x, v.y);
    *(__half2*)(p + 2) = __floats2half2_rn(v.z, v.w);
}

// ---------------------------------------------------------------------------
// Fused prep: segmented grid-stride. Xh = h(X); Wqkvh = h(concat Wq|Wk|Wv);
// Woh = h(Wo); bqkv = concat(bq,bk,bv).
// ---------------------------------------------------------------------------
#define SEG0 (M_ * H_ / 4)
#define SEG1 (H_ * QKV_N / 4)
#define SEG2 (QN_ * H_ / 4)
#define SEG3 (QKV_N / 4)
#define SEG_TOTAL (SEG0 + SEG1 + SEG2 + SEG3)

__global__ __launch_bounds__(256)
void prep_all(const float* __restrict__ X,
              const float* __restrict__ Wq, const float* __restrict__ Wk,
              const float* __restrict__ Wv, const float* __restrict__ Wo,
              const float* __restrict__ bq, const float* __restrict__ bk,
              const float* __restrict__ bv,
              __half* __restrict__ Xh, __half* __restrict__ Wqkvh,
              __half* __restrict__ Woh, float* __restrict__ bqkv)
{
    const int stride = gridDim.x * 256;
    for (int u = blockIdx.x * 256 + threadIdx.x; u < SEG_TOTAL; u += stride) {
        if (u < SEG0) {
            st_half4(Xh + (size_t)u * 4, *(const float4*)(X + (size_t)u * 4));
        } else if (u < SEG0 + SEG1) {
            const int j = u - SEG0;
            const int row = j / (QKV_N / 4);
            const int c = (j - row * (QKV_N / 4)) * 4;
            float4 v;
            if (c < QN_)
                v = *(const float4*)(Wq + (size_t)row * QN_ + c);
            else if (c < QN_ + KN_)
                v = *(const float4*)(Wk + (size_t)row * KN_ + (c - QN_));
            else
                v = *(const float4*)(Wv + (size_t)row * KN_ + (c - QN_ - KN_));
            st_half4(Wqkvh + (size_t)row * QKV_N + c, v);
        } else if (u < SEG0 + SEG1 + SEG2) {
            const int j = u - SEG0 - SEG1;
            st_half4(Woh + (size_t)j * 4, *(const float4*)(Wo + (size_t)j * 4));
        } else {
            const int j = u - SEG0 - SEG1 - SEG2;
            const int c = j * 4;
            float4 v;
            if (c < QN_)            v = *(const float4*)(bq + c);
            else if (c < QN_ + KN_) v = *(const float4*)(bk + c - QN_);
            else                    v = *(const float4*)(bv + c - QN_ - KN_);
            *(float4*)(bqkv + c) = v;
        }
    }
}

// ---------------------------------------------------------------------------
// Shared MMA / ldmatrix helpers
// ---------------------------------------------------------------------------
__device__ __forceinline__ void cp_async16(void* smem_dst, const void* gsrc) {
    unsigned dst = (unsigned)__cvta_generic_to_shared(smem_dst);
    asm volatile("cp.async.cg.shared.global [%0], [%1], 16;" :: "r"(dst), "l"(gsrc));
}

__device__ __forceinline__ void ldsm4(unsigned r[4], const void* p)
{
    unsigned a = (unsigned)__cvta_generic_to_shared(p);
    asm volatile(
        "ldmatrix.sync.aligned.m8n8.x4.shared.b16 {%0,%1,%2,%3}, [%4];"
        : "=r"(r[0]), "=r"(r[1]), "=r"(r[2]), "=r"(r[3]) : "r"(a));
}

__device__ __forceinline__ void ldsm4t(unsigned r[4], const void* p)
{
    unsigned a = (unsigned)__cvta_generic_to_shared(p);
    asm volatile(
        "ldmatrix.sync.aligned.m8n8.x4.trans.shared.b16 {%0,%1,%2,%3}, [%4];"
        : "=r"(r[0]), "=r"(r[1]), "=r"(r[2]), "=r"(r[3]) : "r"(a));
}

__device__ __forceinline__ void mma_fp16(float c[4], const unsigned a[4],
                                         unsigned b0, unsigned b1)
{
    asm volatile(
        "mma.sync.aligned.m16n8k16.row.col.f32.f16.f16.f32 "
        "{%0,%1,%2,%3}, {%4,%5,%6,%7}, {%8,%9}, {%0,%1,%2,%3};"
        : "+f"(c[0]), "+f"(c[1]), "+f"(c[2]), "+f"(c[3])
        : "r"(a[0]), "r"(a[1]), "r"(a[2]), "r"(a[3]), "r"(b0), "r"(b1));
}

__device__ __forceinline__ void mma_bf16(float c[4], const unsigned a[4],
                                         unsigned b0, unsigned b1)
{
    asm volatile(
        "mma.sync.aligned.m16n8k16.row.col.f32.bf16.bf16.f32 "
        "{%0,%1,%2,%3}, {%4,%5,%6,%7}, {%8,%9}, {%0,%1,%2,%3};"
        : "+f"(c[0]), "+f"(c[1]), "+f"(c[2]), "+f"(c[3])
        : "r"(a[0]), "r"(a[1]), "r"(a[2]), "r"(a[3]), "r"(b0), "r"(b1));
}

// ---------------------------------------------------------------------------
// FP16 tensor-core GEMM: C[M][N] = A[M][K] @ B[K][N] + bias, fp32 accum.
// 128x128 CTA tile, 8 warps (64x32 each), BK=16, 3-stage cp.async,
// ldmatrix.x4 (A) + ldmatrix.x4.trans (B).
// ---------------------------------------------------------------------------
#define FA_STR 24                      // halves; 48B rows (16B-aligned, conflict-free)
#define FB_STR 136                     // halves; 272B rows (16B-aligned, conflict-free)
#define FSTG (128 * FA_STR + 16 * FB_STR)   // 3072 + 2176 = 5248 halves

__global__ __launch_bounds__(256)
void gemm_fp16(const __half* __restrict__ A, const __half* __restrict__ B,
               const float* __restrict__ bias, float* __restrict__ C,
               int M, int N, int K)
{
    __shared__ __half sm[3 * FSTG];    // 31488 B

    const int tid  = threadIdx.x;
    const int wid  = tid >> 5;
    const int lane = tid & 31;
    const int warp_m = (wid & 1) * 64;
    const int warp_n = (wid >> 1) * 32;
    const int brow = blockIdx.y * 128;
    const int bcol = blockIdx.x * 128;
    const int lr = lane >> 2;
    const int lc = lane & 3;
    const int ldr  = (lane & 7) + ((lane >> 3) & 1) * 8;   // ldmatrix row 0..15
    const int ldc8 = ((lane >> 4) & 1) * 8;                // ldmatrix col group

    float acc[4][4][4];
#pragma unroll
    for (int mt = 0; mt < 4; mt++)
#pragma unroll
        for (int nt = 0; nt < 4; nt++)
#pragma unroll
            for (int i = 0; i < 4; i++) acc[mt][nt][i] = 0.f;

    const int a_r = tid >> 1,  a_c = (tid & 1) * 8;    // A: 128 rows x 16 halves
    const int b_r = tid >> 4,  b_c = (tid & 15) * 8;   // B: 16 rows x 128 halves

    auto load_stage = [&](int s, int k0) {
        __half* As = sm + s * FSTG;
        __half* Bs = As + 128 * FA_STR;
        cp_async16(&As[a_r * FA_STR + a_c], &A[(size_t)(brow + a_r) * K + k0 + a_c]);
        cp_async16(&Bs[b_r * FB_STR + b_c], &B[(size_t)(k0 + b_r) * N + bcol + b_c]);
        asm volatile("cp.async.commit_group;");
    };

    const int KT = K / 16;
    load_stage(0, 0);
    load_stage(1, 16);

    for (int kt = 0; kt < KT; kt++) {
        const int s = kt % 3;
        if (kt + 1 < KT) asm volatile("cp.async.wait_group 1;");
        else             asm volatile("cp.async.wait_group 0;");
        __syncthreads();

        if (kt + 2 < KT) load_stage((kt + 2) % 3, (kt + 2) * 16);

        const __half* As = sm + s * FSTG;
        const __half* Bs = As + 128 * FA_STR;

        unsigned af[4][4];
#pragma unroll
        for (int mt = 0; mt < 4; mt++)
            ldsm4(af[mt], As + (warp_m + mt * 16 + ldr) * FA_STR + ldc8);

        unsigned bf[4][2];
#pragma unroll
        for (int nt2 = 0; nt2 < 2; nt2++) {
            unsigned t4[4];
            ldsm4t(t4, Bs + ldr * FB_STR + warp_n + nt2 * 16 + ldc8);
            bf[2 * nt2][0]     = t4[0];
            bf[2 * nt2][1]     = t4[1];
            bf[2 * nt2 + 1][0] = t4[2];
            bf[2 * nt2 + 1][1] = t4[3];
        }

#pragma unroll
        for (int mt = 0; mt < 4; mt++)
#pragma unroll
            for (int nt = 0; nt < 4; nt++)
                mma_fp16(acc[mt][nt], af[mt], bf[nt][0], bf[nt][1]);
    }

#pragma unroll
    for (int mt = 0; mt < 4; mt++) {
#pragma unroll
        for (int nt = 0; nt < 4; nt++) {
            const int row0 = brow + warp_m + mt * 16 + lr;
            const int col  = bcol + warp_n + nt * 8 + lc * 2;
            const float b0 = bias ? bias[col]     : 0.f;
            const float b1 = bias ? bias[col + 1] : 0.f;
            float2 v0 = make_float2(acc[mt][nt][0] + b0, acc[mt][nt][1] + b1);
            float2 v1 = make_float2(acc[mt][nt][2] + b0, acc[mt][nt][3] + b1);
            *(float2*)&C[(size_t)row0 * N + col]       = v0;
            *(float2*)&C[(size_t)(row0 + 8) * N + col] = v1;
        }
    }
}

// ---------------------------------------------------------------------------
// RoPE over fused QKV (unchanged from R7)
// ---------------------------------------------------------------------------
__global__ __launch_bounds__(128)
void rope48_kernel(float* __restrict__ QKV,
                   __nv_bfloat16* __restrict__ Khi, __nv_bfloat16* __restrict__ Klo,
                   __nv_bfloat16* __restrict__ Vhi, __nv_bfloat16* __restrict__ Vlo,
                   const int* __restrict__ pos_ids)
{
    const int row  = blockIdx.x;
    const int head = blockIdx.y;
    const int d    = threadIdx.x;

    if (head >= NH_ + NKV_) {
        const int kvh = head - NH_ - NKV_;
        const float v = QKV[(size_t)row * QKV_N + QN_ + KN_ + kvh * HD_ + d];
        const __nv_bfloat16 h = __float2bfloat16(v);
        const size_t off = (size_t)row * KN_ + kvh * HD_;
        Vhi[off + d] = h;
        Vlo[off + d] = __float2bfloat16(v - __bfloat162float(h));
        return;
    }

    const int pos = pos_ids[row];
    const int i = d & 63;
    const float inv_freq = exp2f(-(float)(2 * i) * (1.0f / 128.0f) * 13.28771238f);
    const float ang = (float)pos * inv_freq;
    float c, s;
    sincosf(ang, &s, &c);

    if (head < NH_) {
        float* base = QKV + (size_t)row * QKV_N + head * HD_;
        const float x = base[d];
        const float other = (d < 64) ? -base[d + 64] : base[d - 64];
        const float v = (x * c + other * s) * 0.08838834764831845f;
        __syncthreads();
        base[d] = v;
    } else {
        const int kvh = head - NH_;
        const float* base = QKV + (size_t)row * QKV_N + QN_ + kvh * HD_;
        const float x = base[d];
        const float other = (d < 64) ? -base[d + 64] : base[d - 64];
        const float v = x * c + other * s;
        const __nv_bfloat16 h = __float2bfloat16(v);
        const size_t off = (size_t)row * KN_ + kvh * HD_;
        Khi[off + d] = h;
        Klo[off + d] = __float2bfloat16(v - __bfloat162float(h));
    }
}

// ---------------------------------------------------------------------------
// Tensor-core flash attention, bf16x3 (R7 core; epilogue -> fp16 AO)
// ---------------------------------------------------------------------------
#define BQ 64
#define BK 64
#define KSTR 136
#define ABUF (BK * KSTR * 2)
#define ATT_SMEM (4 * ABUF)

__global__ __launch_bounds__(128)
void attn_mma(const float* __restrict__ QKV,
              const __nv_bfloat16* __restrict__ Khi, const __nv_bfloat16* __restrict__ Klo,
              const __nv_bfloat16* __restrict__ Vhi, const __nv_bfloat16* __restrict__ Vlo,
              __half* __restrict__ AOh)
{
    extern __shared__ char smraw[];
    __nv_bfloat16* sKhi = (__nv_bfloat16*)(smraw);
    __nv_bfloat16* sKlo = (__nv_bfloat16*)(smraw + ABUF);
    __nv_bfloat16* sVhi = (__nv_bfloat16*)(smraw + 2 * ABUF);
    __nv_bfloat16* sVlo = (__nv_bfloat16*)(smraw + 3 * ABUF);

    const int qt = blockIdx.x, h = blockIdx.y, b = blockIdx.z;
    const int q0 = qt * BQ;
    const int kvh = h >> 2;
    const int tid = threadIdx.x;
    const int w = tid >> 5, lane = tid & 31;
    const int lr = lane >> 2, lc = lane & 3;

    const int qrow0 = q0 + w * 16 + lr;
    const int qrow1 = qrow0 + 8;

    unsigned qa_hi[8][4], qa_lo[8][4];
    {
        const float* Q0 = QKV + ((size_t)(b * S_) + qrow0) * QKV_N + h * HD_;
        const float* Q1 = QKV + ((size_t)(b * S_) + qrow1) * QKV_N + h * HD_;
#pragma unroll
        for (int kt = 0; kt < 8; kt++) {
            float2 v;
            v = *(const float2*)(Q0 + kt * 16 + 2 * lc);
            split2(v.x, v.y, qa_hi[kt][0], qa_lo[kt][0]);
            v = *(const float2*)(Q1 + kt * 16 + 2 * lc);
            split2(v.x, v.y, qa_hi[kt][1], qa_lo[kt][1]);
            v = *(const float2*)(Q0 + kt * 16 + 2 * lc + 8);
            split2(v.x, v.y, qa_hi[kt][2], qa_lo[kt][2]);
            v = *(const float2*)(Q1 + kt * 16 + 2 * lc + 8);
            split2(v.x, v.y, qa_hi[kt][3], qa_lo[kt][3]);
        }
    }

    float m0 = -1e30f, m1 = -1e30f, l0 = 0.f, l1 = 0.f;
    float o[16][4];
#pragma unroll
    for (int i = 0; i < 16; i++)
#pragma unroll
        for (int j = 0; j < 4; j++) o[i][j] = 0.f;

    const int nTiles = qt + 1;
    const int wEnd = q0 + w * 16 + 16;
    const int ldr = (lane & 7) + ((lane >> 3) & 1) * 8;
    const int ldc = ((lane >> 4) & 1) * 8;
    const int klr = lane & 7;
    const int kmg = lane >> 3;

    const size_t kv_base = (size_t)(b * S_) * KN_ + kvh * HD_;

    auto load_pair = [&](__nv_bfloat16* dhi, __nv_bfloat16* dlo,
                         const __nv_bfloat16* ghi, const __nv_bfloat16* glo, int kbase) {
        const size_t off = kv_base + (size_t)kbase * KN_;
#pragma unroll
        for (int j = 0; j < 8; j++) {
            const int idx = tid + 128 * j;
            const int row = idx >> 4, c16 = idx & 15;
            const size_t g = off + (size_t)row * KN_ + c16 * 8;
            cp_async16(dhi + row * KSTR + c16 * 8, ghi + g);
            cp_async16(dlo + row * KSTR + c16 * 8, glo + g);
        }
        asm volatile("cp.async.commit_group;");
    };

    load_pair(sKhi, sKlo, Khi, Klo, 0);
    asm volatile("cp.async.wait_group 0;");
    __syncthreads();

    for (int kt = 0; kt < nTiles; kt++) {
        const int kbase = kt * BK;
        const bool active = kbase < wEnd;

        load_pair(sVhi, sVlo, Vhi, Vlo, kbase);

        float sA[8][4];
        unsigned pa_hi[4][4], pa_lo[4][4];

        if (active) {
#pragma unroll
            for (int nt = 0; nt < 8; nt++)
#pragma unroll
                for (int j = 0; j < 4; j++) sA[nt][j] = 0.f;

#pragma unroll
            for (int dkt2 = 0; dkt2 < 4; dkt2++) {
                const int col = dkt2 * 32 + kmg * 8;
#pragma unroll
                for (int nt = 0; nt < 8; nt++) {
                    unsigned bh[4], bl[4];
                    ldsm4(bh, sKhi + (nt * 8 + klr) * KSTR + col);
                    ldsm4(bl, sKlo + (nt * 8 + klr) * KSTR + col);
                    mma_bf16(sA[nt], qa_hi[2 * dkt2],     bh[0], bh[1]);
                    mma_bf16(sA[nt], qa_hi[2 * dkt2],     bl[0], bl[1]);
                    mma_bf16(sA[nt], qa_lo[2 * dkt2],     bh[0], bh[1]);
                    mma_bf16(sA[nt], qa_hi[2 * dkt2 + 1], bh[2], bh[3]);
                    mma_bf16(sA[nt], qa_hi[2 * dkt2 + 1], bl[2], bl[3]);
                    mma_bf16(sA[nt], qa_lo[2 * dkt2 + 1], bh[2], bh[3]);
                }
            }

            if (kbase + BK > qrow0) {
#pragma unroll
                for (int nt = 0; nt < 8; nt++) {
                    const int j0 = kbase + nt * 8 + 2 * lc;
                    if (j0 > qrow0)     sA[nt][0] = -1e30f;
                    if (j0 + 1 > qrow0) sA[nt][1] = -1e30f;
                    if (j0 > qrow1)     sA[nt][2] = -1e30f;
                    if (j0 + 1 > qrow1) sA[nt][3] = -1e30f;
                }
            }

            float mt0 = -1e30f, mt1 = -1e30f;
#pragma unroll
            for (int nt = 0; nt < 8; nt++) {
                mt0 = fmaxf(mt0, fmaxf(sA[nt][0], sA[nt][1]));
                mt1 = fmaxf(mt1, fmaxf(sA[nt][2], sA[nt][3]));
            }
            mt0 = fmaxf(mt0, __shfl_xor_sync(0xffffffffu, mt0, 1));
            mt0 = fmaxf(mt0, __shfl_xor_sync(0xffffffffu, mt0, 2));
            mt1 = fmaxf(mt1, __shfl_xor_sync(0xffffffffu, mt1, 1));
            mt1 = fmaxf(mt1, __shfl_xor_sync(0xffffffffu, mt1, 2));

            const float nm0 = fmaxf(m0, mt0);
            const float nm1 = fmaxf(m1, mt1);
            const float al0 = __expf(m0 - nm0);
            const float al1 = __expf(m1 - nm1);

            float rs0 = 0.f, rs1 = 0.f;
#pragma unroll
            for (int nt = 0; nt < 8; nt++) {
                sA[nt][0] = __expf(sA[nt][0] - nm0);
                sA[nt][1] = __expf(sA[nt][1] - nm0);
                sA[nt][2] = __expf(sA[nt][2] - nm1);
                sA[nt][3] = __expf(sA[nt][3] - nm1);
                rs0 += sA[nt][0] + sA[nt][1];
                rs1 += sA[nt][2] + sA[nt][3];
            }
            rs0 += __shfl_xor_sync(0xffffffffu, rs0, 1);
            rs0 += __shfl_xor_sync(0xffffffffu, rs0, 2);
            rs1 += __shfl_xor_sync(0xffffffffu, rs1, 1);
            rs1 += __shfl_xor_sync(0xffffffffu, rs1, 2);

            l0 = l0 * al0 + rs0;
            l1 = l1 * al1 + rs1;
            m0 = nm0; m1 = nm1;

#pragma unroll
            for (int i = 0; i < 16; i++) {
                o[i][0] *= al0; o[i][1] *= al0;
                o[i][2] *= al1; o[i][3] *= al1;
            }

#pragma unroll
            for (int t = 0; t < 4; t++) {
                split2(sA[2 * t][0],     sA[2 * t][1],     pa_hi[t][0], pa_lo[t][0]);
                split2(sA[2 * t][2],     sA[2 * t][3],     pa_hi[t][1], pa_lo[t][1]);
                split2(sA[2 * t + 1][0], sA[2 * t + 1][1], pa_hi[t][2], pa_lo[t][2]);
                split2(sA[2 * t + 1][2], sA[2 * t + 1][3], pa_hi[t][3], pa_lo[t][3]);
            }
        }

        asm volatile("cp.async.wait_group 0;");
        __syncthreads();

        if (kt + 1 < nTiles) load_pair(sKhi, sKlo, Khi, Klo, kbase + BK);

        if (active) {
#pragma unroll
            for (int t = 0; t < 4; t++) {
#pragma unroll
                for (int np = 0; np < 8; np++) {
                    unsigned vh[4], vl[4];
                    ldsm4t(vh, sVhi + (t * 16 + ldr) * KSTR + np * 16 + ldc);
                    ldsm4t(vl, sVlo + (t * 16 + ldr) * KSTR + np * 16 + ldc);
                    mma_bf16(o[2 * np],     pa_hi[t], vh[0], vh[1]);
                    mma_bf16(o[2 * np],     pa_hi[t], vl[0], vl[1]);
                    mma_bf16(o[2 * np],     pa_lo[t], vh[0], vh[1]);
                    mma_bf16(o[2 * np + 1], pa_hi[t], vh[2], vh[3]);
                    mma_bf16(o[2 * np + 1], pa_hi[t], vl[2], vl[3]);
                    mma_bf16(o[2 * np + 1], pa_lo[t], vh[2], vh[3]);
                }
            }
        }

        asm volatile("cp.async.wait_group 0;");
        __syncthreads();
    }

    // epilogue: normalize + fp16 (feeds fp16 O-GEMM)
    const float il0 = 1.f / l0;
    const float il1 = 1.f / l1;
    __half* O0 = AOh + ((size_t)(b * S_) + qrow0) * QN_ + h * HD_;
    __half* O1 = AOh + ((size_t)(b * S_) + qrow1) * QN_ + h * HD_;
#pragma unroll
    for (int nt = 0; nt < 16; nt++) {
        *(__half2*)(O0 + nt * 8 + 2 * lc) =
            __floats2half2_rn(o[nt][0] * il0, o[nt][1] * il0);
        *(__half2*)(O1 + nt * 8 + 2 * lc) =
            __floats2half2_rn(o[nt][2] * il1, o[nt][3] * il1);
    }
}

// ---------------------------------------------------------------------------
// Launcher
// ---------------------------------------------------------------------------
extern "C" void kernel_launch(void* const* d_in, const int* in_sizes, int n_in,
                              void* d_out, int out_size)
{
    const float* X   = (const float*)d_in[0];
    const int*   pos = (const int*)  d_in[1];
    const float* Wq  = (const float*)d_in[2];
    const float* bq  = (const float*)d_in[3];
    const float* Wk  = (const float*)d_in[4];
    const float* bk  = (const float*)d_in[5];
    const float* Wv  = (const float*)d_in[6];
    const float* bv  = (const float*)d_in[7];
    const float* Wo  = (const float*)d_in[8];
    float* out = (float*)d_out;

    __half *Xh, *Wqkvh, *Woh, *AOh;
    float *bqkv, *QKV;
    __nv_bfloat16 *Khi, *Klo, *Vhi, *Vlo;
    cudaGetSymbolAddress((void**)&Xh,    g_Xh);
    cudaGetSymbolAddress((void**)&Wqkvh, g_Wqkvh);
    cudaGetSymbolAddress((void**)&bqkv,  g_bqkv);
    cudaGetSymbolAddress((void**)&QKV,   g_QKV);
    cudaGetSymbolAddress((void**)&Woh,   g_Woh);
    cudaGetSymbolAddress((void**)&AOh,   g_AOh);
    cudaGetSymbolAddress((void**)&Khi,   g_Khi);
    cudaGetSymbolAddress((void**)&Klo,   g_Klo);
    cudaGetSymbolAddress((void**)&Vhi,   g_Vhi);
    cudaGetSymbolAddress((void**)&Vlo,   g_Vlo);

    cudaFuncSetAttribute(attn_mma, cudaFuncAttributeMaxDynamicSharedMemorySize, ATT_SMEM);

    // Fused prep (fp16 rounding + concat + bias) in one launch
    prep_all<<<1184, 256>>>(X, Wq, Wk, Wv, Wo, bq, bk, bv, Xh, Wqkvh, Woh, bqkv);

    // Fused QKV projection (fp16 tensor cores, fp32 accumulate)
    gemm_fp16<<<dim3(QKV_N / 128, M_ / 128), 256>>>(Xh, Wqkvh, bqkv, QKV, M_, QKV_N, H_);

    // RoPE + K/V split
    rope48_kernel<<<dim3(M_, NH_ + 2 * NKV_), 128>>>(QKV, Khi, Klo, Vhi, Vlo, pos);

    // Attention (bf16x3), writes fp16 AO
    attn_mma<<<dim3(S_ / BQ, NH_, B_), 128, ATT_SMEM>>>(QKV, Khi, Klo, Vhi, Vlo, AOh);

    // Output projection (fp16 tensor cores)
    gemm_fp16<<<dim3(QN_ / 128, M_ / 128), 256>>>(AOh, Woh, nullptr, out, M_, QN_, H_);
}

// round 10
// speedup vs baseline: 1.8566x; 1.1571x over previous
#include <cuda_runtime.h>
#include <cuda_bf16.h>
#include <cuda_fp16.h>
#include <math.h>
#include <stdint.h>

// Problem constants
#define B_  2
#define S_  2048
#define H_  4096
#define NH_ 32
#define NKV_ 8
#define HD_ 128
#define M_  (B_ * S_)          // 4096 rows
#define QN_ (NH_ * HD_)        // 4096
#define KN_ (NKV_ * HD_)       // 1024
#define QKV_N (QN_ + 2 * KN_)  // 6144

// Scratch (device globals; no allocations allowed)
__device__ __half g_Xh[M_ * H_];          // fp16-rounded X
__device__ __half g_Wqkvh[H_ * QKV_N];    // concat fp16 weights [H][6144]
__device__ float  g_bqkv[QKV_N];
__device__ float  g_QKV[M_ * QKV_N];      // fused projection output (fp32)
__device__ __half g_Woh[QN_ * H_];        // fp16 Wo
__device__ __half g_AOh[M_ * QN_];        // attention output (fp16)
__device__ __half g_Khi[M_ * KN_], g_Klo[M_ * KN_];   // K fp16 hi/lo
__device__ __half g_Vhi[M_ * KN_], g_Vlo[M_ * KN_];   // V fp16 hi/lo

__device__ __forceinline__ void split2h(float x, float y, unsigned& hi, unsigned& lo)
{
    __half2 h = __floats2half2_rn(x, y);
    float hx = __low2float(h), hy = __high2float(h);
    __half2 l = __floats2half2_rn(x - hx, y - hy);
    hi = *(unsigned*)&h;
    lo = *(unsigned*)&l;
}

__device__ __forceinline__ void st_half4(__half* p, float4 v)
{
    *(__half2*)(p)     = __floats2half2_rn(v.x, v.y);
    *(__half2*)(p + 2) = __floats2half2_rn(v.z, v.w);
}

// ---------------------------------------------------------------------------
// Fused prep (unchanged from R9)
// ---------------------------------------------------------------------------
#define SEG0 (M_ * H_ / 4)
#define SEG1 (H_ * QKV_N / 4)
#define SEG2 (QN_ * H_ / 4)
#define SEG3 (QKV_N / 4)
#define SEG_TOTAL (SEG0 + SEG1 + SEG2 + SEG3)

__global__ __launch_bounds__(256)
void prep_all(const float* __restrict__ X,
              const float* __restrict__ Wq, const float* __restrict__ Wk,
              const float* __restrict__ Wv, const float* __restrict__ Wo,
              const float* __restrict__ bq, const float* __restrict__ bk,
              const float* __restrict__ bv,
              __half* __restrict__ Xh, __half* __restrict__ Wqkvh,
              __half* __restrict__ Woh, float* __restrict__ bqkv)
{
    const int stride = gridDim.x * 256;
    for (int u = blockIdx.x * 256 + threadIdx.x; u < SEG_TOTAL; u += stride) {
        if (u < SEG0) {
            st_half4(Xh + (size_t)u * 4, *(const float4*)(X + (size_t)u * 4));
        } else if (u < SEG0 + SEG1) {
            const int j = u - SEG0;
            const int row = j / (QKV_N / 4);
            const int c = (j - row * (QKV_N / 4)) * 4;
            float4 v;
            if (c < QN_)
                v = *(const float4*)(Wq + (size_t)row * QN_ + c);
            else if (c < QN_ + KN_)
                v = *(const float4*)(Wk + (size_t)row * KN_ + (c - QN_));
            else
                v = *(const float4*)(Wv + (size_t)row * KN_ + (c - QN_ - KN_));
            st_half4(Wqkvh + (size_t)row * QKV_N + c, v);
        } else if (u < SEG0 + SEG1 + SEG2) {
            const int j = u - SEG0 - SEG1;
            st_half4(Woh + (size_t)j * 4, *(const float4*)(Wo + (size_t)j * 4));
        } else {
            const int j = u - SEG0 - SEG1 - SEG2;
            const int c = j * 4;
            float4 v;
            if (c < QN_)            v = *(const float4*)(bq + c);
            else if (c < QN_ + KN_) v = *(const float4*)(bk + c - QN_);
            else                    v = *(const float4*)(bv + c - QN_ - KN_);
            *(float4*)(bqkv + c) = v;
        }
    }
}

// ---------------------------------------------------------------------------
// Shared MMA / ldmatrix helpers
// ---------------------------------------------------------------------------
__device__ __forceinline__ void cp_async16(void* smem_dst, const void* gsrc) {
    unsigned dst = (unsigned)__cvta_generic_to_shared(smem_dst);
    asm volatile("cp.async.cg.shared.global [%0], [%1], 16;" :: "r"(dst), "l"(gsrc));
}

__device__ __forceinline__ void ldsm4(unsigned r[4], const void* p)
{
    unsigned a = (unsigned)__cvta_generic_to_shared(p);
    asm volatile(
        "ldmatrix.sync.aligned.m8n8.x4.shared.b16 {%0,%1,%2,%3}, [%4];"
        : "=r"(r[0]), "=r"(r[1]), "=r"(r[2]), "=r"(r[3]) : "r"(a));
}

__device__ __forceinline__ void ldsm4t(unsigned r[4], const void* p)
{
    unsigned a = (unsigned)__cvta_generic_to_shared(p);
    asm volatile(
        "ldmatrix.sync.aligned.m8n8.x4.trans.shared.b16 {%0,%1,%2,%3}, [%4];"
        : "=r"(r[0]), "=r"(r[1]), "=r"(r[2]), "=r"(r[3]) : "r"(a));
}

__device__ __forceinline__ void mma_fp16(float c[4], const unsigned a[4],
                                         unsigned b0, unsigned b1)
{
    asm volatile(
        "mma.sync.aligned.m16n8k16.row.col.f32.f16.f16.f32 "
        "{%0,%1,%2,%3}, {%4,%5,%6,%7}, {%8,%9}, {%0,%1,%2,%3};"
        : "+f"(c[0]), "+f"(c[1]), "+f"(c[2]), "+f"(c[3])
        : "r"(a[0]), "r"(a[1]), "r"(a[2]), "r"(a[3]), "r"(b0), "r"(b1));
}

// ---------------------------------------------------------------------------
// FP16 tensor-core GEMM: 128x128 tile, 8 warps (64x32), BK=32, 3-stage
// cp.async in dynamic smem (56.8 KB). fp32 accumulate.
// ---------------------------------------------------------------------------
#define FA_STR 40                      // halves; 80B rows (conflict-free ldsm)
#define FB_STR 136                     // halves; 272B rows (conflict-free ldsm.trans)
#define FSTG (128 * FA_STR + 32 * FB_STR)   // 5120 + 4352 = 9472 halves
#define G_SMEM (3 * FSTG * 2)               // 56832 bytes

__global__ __launch_bounds__(256)
void gemm_fp16(const __half* __restrict__ A, const __half* __restrict__ B,
               const float* __restrict__ bias, float* __restrict__ C,
               int M, int N, int K)
{
    extern __shared__ __half gsm[];

    const int tid  = threadIdx.x;
    const int wid  = tid >> 5;
    const int lane = tid & 31;
    const int warp_m = (wid & 1) * 64;
    const int warp_n = (wid >> 1) * 32;
    const int brow = blockIdx.y * 128;
    const int bcol = blockIdx.x * 128;
    const int lr = lane >> 2;
    const int lc = lane & 3;
    const int ldr  = (lane & 7) + ((lane >> 3) & 1) * 8;
    const int ldc8 = ((lane >> 4) & 1) * 8;

    float acc[4][4][4];
#pragma unroll
    for (int mt = 0; mt < 4; mt++)
#pragma unroll
        for (int nt = 0; nt < 4; nt++)
#pragma unroll
            for (int i = 0; i < 4; i++) acc[mt][nt][i] = 0.f;

    auto load_stage = [&](int s, int k0) {
        __half* As = gsm + s * FSTG;
        __half* Bs = As + 128 * FA_STR;
#pragma unroll
        for (int it = 0; it < 2; it++) {       // A: 128 x 32 halves = 512 chunks
            const int idx = tid + 256 * it;
            const int r = idx >> 2, c = (idx & 3) * 8;
            cp_async16(&As[r * FA_STR + c], &A[(size_t)(brow + r) * K + k0 + c]);
        }
#pragma unroll
        for (int it = 0; it < 2; it++) {       // B: 32 x 128 halves = 512 chunks
            const int idx = tid + 256 * it;
            const int r = idx >> 4, c = (idx & 15) * 8;
            cp_async16(&Bs[r * FB_STR + c], &B[(size_t)(k0 + r) * N + bcol + c]);
        }
        asm volatile("cp.async.commit_group;");
    };

    const int KT = K / 32;
    load_stage(0, 0);
    load_stage(1, 32);

    for (int kt = 0; kt < KT; kt++) {
        const int s = kt % 3;
        if (kt + 1 < KT) asm volatile("cp.async.wait_group 1;");
        else             asm volatile("cp.async.wait_group 0;");
        __syncthreads();

        if (kt + 2 < KT) load_stage((kt + 2) % 3, (kt + 2) * 32);

        const __half* As = gsm + s * FSTG;
        const __half* Bs = As + 128 * FA_STR;

#pragma unroll
        for (int ks = 0; ks < 2; ks++) {
            unsigned af[4][4];
#pragma unroll
            for (int mt = 0; mt < 4; mt++)
                ldsm4(af[mt], As + (warp_m + mt * 16 + ldr) * FA_STR + ks * 16 + ldc8);

            unsigned bf[4][2];
#pragma unroll
            for (int nt2 = 0; nt2 < 2; nt2++) {
                unsigned t4[4];
                ldsm4t(t4, Bs + (ks * 16 + ldr) * FB_STR + warp_n + nt2 * 16 + ldc8);
                bf[2 * nt2][0]     = t4[0];
                bf[2 * nt2][1]     = t4[1];
                bf[2 * nt2 + 1][0] = t4[2];
                bf[2 * nt2 + 1][1] = t4[3];
            }

#pragma unroll
            for (int mt = 0; mt < 4; mt++)
#pragma unroll
                for (int nt = 0; nt < 4; nt++)
                    mma_fp16(acc[mt][nt], af[mt], bf[nt][0], bf[nt][1]);
        }
    }

#pragma unroll
    for (int mt = 0; mt < 4; mt++) {
#pragma unroll
        for (int nt = 0; nt < 4; nt++) {
            const int row0 = brow + warp_m + mt * 16 + lr;
            const int col  = bcol + warp_n + nt * 8 + lc * 2;
            const float b0 = bias ? bias[col]     : 0.f;
            const float b1 = bias ? bias[col + 1] : 0.f;
            float2 v0 = make_float2(acc[mt][nt][0] + b0, acc[mt][nt][1] + b1);
            float2 v1 = make_float2(acc[mt][nt][2] + b0, acc[mt][nt][3] + b1);
            *(float2*)&C[(size_t)row0 * N + col]       = v0;
            *(float2*)&C[(size_t)(row0 + 8) * N + col] = v1;
        }
    }
}

// ---------------------------------------------------------------------------
// RoPE over fused QKV: Q in-place (pre-scaled); K rotated -> fp16 hi/lo;
// V -> fp16 hi/lo.
// ---------------------------------------------------------------------------
__global__ __launch_bounds__(128)
void rope48_kernel(float* __restrict__ QKV,
                   __half* __restrict__ Khi, __half* __restrict__ Klo,
                   __half* __restrict__ Vhi, __half* __restrict__ Vlo,
                   const int* __restrict__ pos_ids)
{
    const int row  = blockIdx.x;
    const int head = blockIdx.y;
    const int d    = threadIdx.x;

    if (head >= NH_ + NKV_) {
        const int kvh = head - NH_ - NKV_;
        const float v = QKV[(size_t)row * QKV_N + QN_ + KN_ + kvh * HD_ + d];
        const __half h = __float2half_rn(v);
        const size_t off = (size_t)row * KN_ + kvh * HD_;
        Vhi[off + d] = h;
        Vlo[off + d] = __float2half_rn(v - __half2float(h));
        return;
    }

    const int pos = pos_ids[row];
    const int i = d & 63;
    const float inv_freq = exp2f(-(float)(2 * i) * (1.0f / 128.0f) * 13.28771238f);
    const float ang = (float)pos * inv_freq;
    float c, s;
    sincosf(ang, &s, &c);

    if (head < NH_) {
        float* base = QKV + (size_t)row * QKV_N + head * HD_;
        const float x = base[d];
        const float other = (d < 64) ? -base[d + 64] : base[d - 64];
        const float v = (x * c + other * s) * 0.08838834764831845f;
        __syncthreads();
        base[d] = v;
    } else {
        const int kvh = head - NH_;
        const float* base = QKV + (size_t)row * QKV_N + QN_ + kvh * HD_;
        const float x = base[d];
        const float other = (d < 64) ? -base[d + 64] : base[d - 64];
        const float v = x * c + other * s;
        const __half h = __float2half_rn(v);
        const size_t off = (size_t)row * KN_ + kvh * HD_;
        Khi[off + d] = h;
        Klo[off + d] = __float2half_rn(v - __half2float(h));
    }
}

// ---------------------------------------------------------------------------
// Tensor-core flash attention, fp16: QK = 3-MMA hi/lo (2^-22), PV = 2-MMA
// (P single fp16, V hi/lo). 64 queries/block, 4 warps, 64-key tiles.
// ---------------------------------------------------------------------------
#define BQ 64
#define BK 64
#define KSTR 136
#define ABUF (BK * KSTR * 2)
#define ATT_SMEM (4 * ABUF)

__global__ __launch_bounds__(128)
void attn_mma(const float* __restrict__ QKV,
              const __half* __restrict__ Khi, const __half* __restrict__ Klo,
              const __half* __restrict__ Vhi, const __half* __restrict__ Vlo,
              __half* __restrict__ AOh)
{
    extern __shared__ char smraw[];
    __half* sKhi = (__half*)(smraw);
    __half* sKlo = (__half*)(smraw + ABUF);
    __half* sVhi = (__half*)(smraw + 2 * ABUF);
    __half* sVlo = (__half*)(smraw + 3 * ABUF);

    const int qt = blockIdx.x, h = blockIdx.y, b = blockIdx.z;
    const int q0 = qt * BQ;
    const int kvh = h >> 2;
    const int tid = threadIdx.x;
    const int w = tid >> 5, lane = tid & 31;
    const int lr = lane >> 2, lc = lane & 3;

    const int qrow0 = q0 + w * 16 + lr;
    const int qrow1 = qrow0 + 8;

    // Q fragments (pre-scaled by rope), fp16 hi/lo split, in registers
    unsigned qa_hi[8][4], qa_lo[8][4];
    {
        const float* Q0 = QKV + ((size_t)(b * S_) + qrow0) * QKV_N + h * HD_;
        const float* Q1 = QKV + ((size_t)(b * S_) + qrow1) * QKV_N + h * HD_;
#pragma unroll
        for (int kt = 0; kt < 8; kt++) {
            float2 v;
            v = *(const float2*)(Q0 + kt * 16 + 2 * lc);
            split2h(v.x, v.y, qa_hi[kt][0], qa_lo[kt][0]);
            v = *(const float2*)(Q1 + kt * 16 + 2 * lc);
            split2h(v.x, v.y, qa_hi[kt][1], qa_lo[kt][1]);
            v = *(const float2*)(Q0 + kt * 16 + 2 * lc + 8);
            split2h(v.x, v.y, qa_hi[kt][2], qa_lo[kt][2]);
            v = *(const float2*)(Q1 + kt * 16 + 2 * lc + 8);
            split2h(v.x, v.y, qa_hi[kt][3], qa_lo[kt][3]);
        }
    }

    float m0 = -1e30f, m1 = -1e30f, l0 = 0.f, l1 = 0.f;
    float o[16][4];
#pragma unroll
    for (int i = 0; i < 16; i++)
#pragma unroll
        for (int j = 0; j < 4; j++) o[i][j] = 0.f;

    const int nTiles = qt + 1;
    const int wEnd = q0 + w * 16 + 16;
    const int ldr = (lane & 7) + ((lane >> 3) & 1) * 8;
    const int ldc = ((lane >> 4) & 1) * 8;
    const int klr = lane & 7;
    const int kmg = lane >> 3;

    const size_t kv_base = (size_t)(b * S_) * KN_ + kvh * HD_;

    auto load_pair = [&](__half* dhi, __half* dlo,
                         const __half* ghi, const __half* glo, int kbase) {
        const size_t off = kv_base + (size_t)kbase * KN_;
#pragma unroll
        for (int j = 0; j < 8; j++) {
            const int idx = tid + 128 * j;
            const int row = idx >> 4, c16 = idx & 15;
            const size_t g = off + (size_t)row * KN_ + c16 * 8;
            cp_async16(dhi + row * KSTR + c16 * 8, ghi + g);
            cp_async16(dlo + row * KSTR + c16 * 8, glo + g);
        }
        asm volatile("cp.async.commit_group;");
    };

    load_pair(sKhi, sKlo, Khi, Klo, 0);
    asm volatile("cp.async.wait_group 0;");
    __syncthreads();

    for (int kt = 0; kt < nTiles; kt++) {
        const int kbase = kt * BK;
        const bool active = kbase < wEnd;

        load_pair(sVhi, sVlo, Vhi, Vlo, kbase);

        float sA[8][4];
        unsigned pa[4][4];

        if (active) {
#pragma unroll
            for (int nt = 0; nt < 8; nt++)
#pragma unroll
                for (int j = 0; j < 4; j++) sA[nt][j] = 0.f;

#pragma unroll
            for (int dkt2 = 0; dkt2 < 4; dkt2++) {
                const int col = dkt2 * 32 + kmg * 8;
#pragma unroll
                for (int nt = 0; nt < 8; nt++) {
                    unsigned bh[4], bl[4];
                    ldsm4(bh, sKhi + (nt * 8 + klr) * KSTR + col);
                    ldsm4(bl, sKlo + (nt * 8 + klr) * KSTR + col);
                    mma_fp16(sA[nt], qa_hi[2 * dkt2],     bh[0], bh[1]);
                    mma_fp16(sA[nt], qa_hi[2 * dkt2],     bl[0], bl[1]);
                    mma_fp16(sA[nt], qa_lo[2 * dkt2],     bh[0], bh[1]);
                    mma_fp16(sA[nt], qa_hi[2 * dkt2 + 1], bh[2], bh[3]);
                    mma_fp16(sA[nt], qa_hi[2 * dkt2 + 1], bl[2], bl[3]);
                    mma_fp16(sA[nt], qa_lo[2 * dkt2 + 1], bh[2], bh[3]);
                }
            }

            if (kbase + BK > qrow0) {
#pragma unroll
                for (int nt = 0; nt < 8; nt++) {
                    const int j0 = kbase + nt * 8 + 2 * lc;
                    if (j0 > qrow0)     sA[nt][0] = -1e30f;
                    if (j0 + 1 > qrow0) sA[nt][1] = -1e30f;
                    if (j0 > qrow1)     sA[nt][2] = -1e30f;
                    if (j0 + 1 > qrow1) sA[nt][3] = -1e30f;
                }
            }

            float mt0 = -1e30f, mt1 = -1e30f;
#pragma unroll
            for (int nt = 0; nt < 8; nt++) {
                mt0 = fmaxf(mt0, fmaxf(sA[nt][0], sA[nt][1]));
                mt1 = fmaxf(mt1, fmaxf(sA[nt][2], sA[nt][3]));
            }
            mt0 = fmaxf(mt0, __shfl_xor_sync(0xffffffffu, mt0, 1));
            mt0 = fmaxf(mt0, __shfl_xor_sync(0xffffffffu, mt0, 2));
            mt1 = fmaxf(mt1, __shfl_xor_sync(0xffffffffu, mt1, 1));
            mt1 = fmaxf(mt1, __shfl_xor_sync(0xffffffffu, mt1, 2));

            const float nm0 = fmaxf(m0, mt0);
            const float nm1 = fmaxf(m1, mt1);
            const float al0 = __expf(m0 - nm0);
            const float al1 = __expf(m1 - nm1);

            float rs0 = 0.f, rs1 = 0.f;
#pragma unroll
            for (int nt = 0; nt < 8; nt++) {
                sA[nt][0] = __expf(sA[nt][0] - nm0);
                sA[nt][1] = __expf(sA[nt][1] - nm0);
                sA[nt][2] = __expf(sA[nt][2] - nm1);
                sA[nt][3] = __expf(sA[nt][3] - nm1);
                rs0 += sA[nt][0] + sA[nt][1];
                rs1 += sA[nt][2] + sA[nt][3];
            }
            rs0 += __shfl_xor_sync(0xffffffffu, rs0, 1);
            rs0 += __shfl_xor_sync(0xffffffffu, rs0, 2);
            rs1 += __shfl_xor_sync(0xffffffffu, rs1, 1);
            rs1 += __shfl_xor_sync(0xffffffffu, rs1, 2);

            l0 = l0 * al0 + rs0;
            l1 = l1 * al1 + rs1;
            m0 = nm0; m1 = nm1;

#pragma unroll
            for (int i = 0; i < 16; i++) {
                o[i][0] *= al0; o[i][1] *= al0;
                o[i][2] *= al1; o[i][3] *= al1;
            }

            // P -> single fp16 A-fragments
#pragma unroll
            for (int t = 0; t < 4; t++) {
                __half2 p0 = __floats2half2_rn(sA[2 * t][0],     sA[2 * t][1]);
                __half2 p1 = __floats2half2_rn(sA[2 * t][2],     sA[2 * t][3]);
                __half2 p2 = __floats2half2_rn(sA[2 * t + 1][0], sA[2 * t + 1][1]);
                __half2 p3 = __floats2half2_rn(sA[2 * t + 1][2], sA[2 * t + 1][3]);
                pa[t][0] = *(unsigned*)&p0;
                pa[t][1] = *(unsigned*)&p1;
                pa[t][2] = *(unsigned*)&p2;
                pa[t][3] = *(unsigned*)&p3;
            }
        }

        asm volatile("cp.async.wait_group 0;");
        __syncthreads();

        if (kt + 1 < nTiles) load_pair(sKhi, sKlo, Khi, Klo, kbase + BK);

        if (active) {
#pragma unroll
            for (int t = 0; t < 4; t++) {
#pragma unroll
                for (int np = 0; np < 8; np++) {
                    unsigned vh[4], vl[4];
                    ldsm4t(vh, sVhi + (t * 16 + ldr) * KSTR + np * 16 + ldc);
                    ldsm4t(vl, sVlo + (t * 16 + ldr) * KSTR + np * 16 + ldc);
                    mma_fp16(o[2 * np],     pa[t], vh[0], vh[1]);
                    mma_fp16(o[2 * np],     pa[t], vl[0], vl[1]);
                    mma_fp16(o[2 * np + 1], pa[t], vh[2], vh[3]);
                    mma_fp16(o[2 * np + 1], pa[t], vl[2], vl[3]);
                }
            }
        }

        asm volatile("cp.async.wait_group 0;");
        __syncthreads();
    }

    // epilogue: normalize + fp16 (feeds fp16 O-GEMM)
    const float il0 = 1.f / l0;
    const float il1 = 1.f / l1;
    __half* O0 = AOh + ((size_t)(b * S_) + qrow0) * QN_ + h * HD_;
    __half* O1 = AOh + ((size_t)(b * S_) + qrow1) * QN_ + h * HD_;
#pragma unroll
    for (int nt = 0; nt < 16; nt++) {
        *(__half2*)(O0 + nt * 8 + 2 * lc) =
            __floats2half2_rn(o[nt][0] * il0, o[nt][1] * il0);
        *(__half2*)(O1 + nt * 8 + 2 * lc) =
            __floats2half2_rn(o[nt][2] * il1, o[nt][3] * il1);
    }
}

// ---------------------------------------------------------------------------
// Launcher
// ---------------------------------------------------------------------------
extern "C" void kernel_launch(void* const* d_in, const int* in_sizes, int n_in,
                              void* d_out, int out_size)
{
    const float* X   = (const float*)d_in[0];
    const int*   pos = (const int*)  d_in[1];
    const float* Wq  = (const float*)d_in[2];
    const float* bq  = (const float*)d_in[3];
    const float* Wk  = (const float*)d_in[4];
    const float* bk  = (const float*)d_in[5];
    const float* Wv  = (const float*)d_in[6];
    const float* bv  = (const float*)d_in[7];
    const float* Wo  = (const float*)d_in[8];
    float* out = (float*)d_out;

    __half *Xh, *Wqkvh, *Woh, *AOh, *Khi, *Klo, *Vhi, *Vlo;
    float *bqkv, *QKV;
    cudaGetSymbolAddress((void**)&Xh,    g_Xh);
    cudaGetSymbolAddress((void**)&Wqkvh, g_Wqkvh);
    cudaGetSymbolAddress((void**)&bqkv,  g_bqkv);
    cudaGetSymbolAddress((void**)&QKV,   g_QKV);
    cudaGetSymbolAddress((void**)&Woh,   g_Woh);
    cudaGetSymbolAddress((void**)&AOh,   g_AOh);
    cudaGetSymbolAddress((void**)&Khi,   g_Khi);
    cudaGetSymbolAddress((void**)&Klo,   g_Klo);
    cudaGetSymbolAddress((void**)&Vhi,   g_Vhi);
    cudaGetSymbolAddress((void**)&Vlo,   g_Vlo);

    cudaFuncSetAttribute(attn_mma,  cudaFuncAttributeMaxDynamicSharedMemorySize, ATT_SMEM);
    cudaFuncSetAttribute(gemm_fp16, cudaFuncAttributeMaxDynamicSharedMemorySize, G_SMEM);

    // Fused prep (fp16 rounding + concat + bias) in one launch
    prep_all<<<1184, 256>>>(X, Wq, Wk, Wv, Wo, bq, bk, bv, Xh, Wqkvh, Woh, bqkv);

    // Fused QKV projection (fp16 tensor cores, fp32 accumulate)
    gemm_fp16<<<dim3(QKV_N / 128, M_ / 128), 256, G_SMEM>>>(
        Xh, Wqkvh, bqkv, QKV, M_, QKV_N, H_);

    // RoPE + K/V fp16 split
    rope48_kernel<<<dim3(M_, NH_ + 2 * NKV_), 128>>>(QKV, Khi, Klo, Vhi, Vlo, pos);

    // Attention (fp16 x3 QK, x2 PV), writes fp16 AO
    attn_mma<<<dim3(S_ / BQ, NH_, B_), 128, ATT_SMEM>>>(QKV, Khi, Klo, Vhi, Vlo, AOh);

    // Output projection (fp16 tensor cores)
    gemm_fp16<<<dim3(QN_ / 128, M_ / 128), 256, G_SMEM>>>(
        AOh, Woh, nullptr, out, M_, QN_, H_);
}

// round 11
// speedup vs baseline: 2.0013x; 1.0779x over previous
#include <cuda_runtime.h>
#include <cuda_bf16.h>
#include <cuda_fp16.h>
#include <math.h>
#include <stdint.h>

// Problem constants
#define B_  2
#define S_  2048
#define H_  4096
#define NH_ 32
#define NKV_ 8
#define HD_ 128
#define M_  (B_ * S_)          // 4096 rows
#define QN_ (NH_ * HD_)        // 4096
#define KN_ (NKV_ * HD_)       // 1024
#define QKV_N (QN_ + 2 * KN_)  // 6144

// Scratch (device globals; no allocations allowed)
__device__ __half g_Xh[M_ * H_];          // fp16-rounded X
__device__ __half g_Wqkvh[H_ * QKV_N];    // concat fp16 weights [H][6144]
__device__ float  g_bqkv[QKV_N];
__device__ float  g_QKV[M_ * QKV_N];      // fused projection output (fp32)
__device__ __half g_Woh[QN_ * H_];        // fp16 Wo
__device__ __half g_AOh[M_ * QN_];        // attention output (fp16)
__device__ __half g_Qhi[M_ * QN_], g_Qlo[M_ * QN_];   // roped+scaled Q hi/lo
__device__ __half g_Khi[M_ * KN_], g_Klo[M_ * KN_];   // roped K hi/lo
__device__ __half g_Vhi[M_ * KN_];                    // V single fp16

__device__ __forceinline__ void st_half4(__half* p, float4 v)
{
    *(__half2*)(p)     = __floats2half2_rn(v.x, v.y);
    *(__half2*)(p + 2) = __floats2half2_rn(v.z, v.w);
}

// ---------------------------------------------------------------------------
// Fused prep (unchanged from R10)
// ---------------------------------------------------------------------------
#define SEG0 (M_ * H_ / 4)
#define SEG1 (H_ * QKV_N / 4)
#define SEG2 (QN_ * H_ / 4)
#define SEG3 (QKV_N / 4)
#define SEG_TOTAL (SEG0 + SEG1 + SEG2 + SEG3)

__global__ __launch_bounds__(256)
void prep_all(const float* __restrict__ X,
              const float* __restrict__ Wq, const float* __restrict__ Wk,
              const float* __restrict__ Wv, const float* __restrict__ Wo,
              const float* __restrict__ bq, const float* __restrict__ bk,
              const float* __restrict__ bv,
              __half* __restrict__ Xh, __half* __restrict__ Wqkvh,
              __half* __restrict__ Woh, float* __restrict__ bqkv)
{
    const int stride = gridDim.x * 256;
    for (int u = blockIdx.x * 256 + threadIdx.x; u < SEG_TOTAL; u += stride) {
        if (u < SEG0) {
            st_half4(Xh + (size_t)u * 4, *(const float4*)(X + (size_t)u * 4));
        } else if (u < SEG0 + SEG1) {
            const int j = u - SEG0;
            const int row = j / (QKV_N / 4);
            const int c = (j - row * (QKV_N / 4)) * 4;
            float4 v;
            if (c < QN_)
                v = *(const float4*)(Wq + (size_t)row * QN_ + c);
            else if (c < QN_ + KN_)
                v = *(const float4*)(Wk + (size_t)row * KN_ + (c - QN_));
            else
                v = *(const float4*)(Wv + (size_t)row * KN_ + (c - QN_ - KN_));
            st_half4(Wqkvh + (size_t)row * QKV_N + c, v);
        } else if (u < SEG0 + SEG1 + SEG2) {
            const int j = u - SEG0 - SEG1;
            st_half4(Woh + (size_t)j * 4, *(const float4*)(Wo + (size_t)j * 4));
        } else {
            const int j = u - SEG0 - SEG1 - SEG2;
            const int c = j * 4;
            float4 v;
            if (c < QN_)            v = *(const float4*)(bq + c);
            else if (c < QN_ + KN_) v = *(const float4*)(bk + c - QN_);
            else                    v = *(const float4*)(bv + c - QN_ - KN_);
            *(float4*)(bqkv + c) = v;
        }
    }
}

// ---------------------------------------------------------------------------
// Shared MMA / ldmatrix helpers
// ---------------------------------------------------------------------------
__device__ __forceinline__ void cp_async16(void* smem_dst, const void* gsrc) {
    unsigned dst = (unsigned)__cvta_generic_to_shared(smem_dst);
    asm volatile("cp.async.cg.shared.global [%0], [%1], 16;" :: "r"(dst), "l"(gsrc));
}

__device__ __forceinline__ void ldsm4(unsigned r[4], const void* p)
{
    unsigned a = (unsigned)__cvta_generic_to_shared(p);
    asm volatile(
        "ldmatrix.sync.aligned.m8n8.x4.shared.b16 {%0,%1,%2,%3}, [%4];"
        : "=r"(r[0]), "=r"(r[1]), "=r"(r[2]), "=r"(r[3]) : "r"(a));
}

__device__ __forceinline__ void ldsm4t(unsigned r[4], const void* p)
{
    unsigned a = (unsigned)__cvta_generic_to_shared(p);
    asm volatile(
        "ldmatrix.sync.aligned.m8n8.x4.trans.shared.b16 {%0,%1,%2,%3}, [%4];"
        : "=r"(r[0]), "=r"(r[1]), "=r"(r[2]), "=r"(r[3]) : "r"(a));
}

__device__ __forceinline__ void mma_fp16(float c[4], const unsigned a[4],
                                         unsigned b0, unsigned b1)
{
    asm volatile(
        "mma.sync.aligned.m16n8k16.row.col.f32.f16.f16.f32 "
        "{%0,%1,%2,%3}, {%4,%5,%6,%7}, {%8,%9}, {%0,%1,%2,%3};"
        : "+f"(c[0]), "+f"(c[1]), "+f"(c[2]), "+f"(c[3])
        : "r"(a[0]), "r"(a[1]), "r"(a[2]), "r"(a[3]), "r"(b0), "r"(b1));
}

// ---------------------------------------------------------------------------
// FP16 tensor-core GEMM (unchanged from R10): 128x128, BK=32, 3-stage.
// ---------------------------------------------------------------------------
#define FA_STR 40
#define FB_STR 136
#define FSTG (128 * FA_STR + 32 * FB_STR)
#define G_SMEM (3 * FSTG * 2)

__global__ __launch_bounds__(256)
void gemm_fp16(const __half* __restrict__ A, const __half* __restrict__ B,
               const float* __restrict__ bias, float* __restrict__ C,
               int M, int N, int K)
{
    extern __shared__ __half gsm[];

    const int tid  = threadIdx.x;
    const int wid  = tid >> 5;
    const int lane = tid & 31;
    const int warp_m = (wid & 1) * 64;
    const int warp_n = (wid >> 1) * 32;
    const int brow = blockIdx.y * 128;
    const int bcol = blockIdx.x * 128;
    const int lr = lane >> 2;
    const int lc = lane & 3;
    const int ldr  = (lane & 7) + ((lane >> 3) & 1) * 8;
    const int ldc8 = ((lane >> 4) & 1) * 8;

    float acc[4][4][4];
#pragma unroll
    for (int mt = 0; mt < 4; mt++)
#pragma unroll
        for (int nt = 0; nt < 4; nt++)
#pragma unroll
            for (int i = 0; i < 4; i++) acc[mt][nt][i] = 0.f;

    auto load_stage = [&](int s, int k0) {
        __half* As = gsm + s * FSTG;
        __half* Bs = As + 128 * FA_STR;
#pragma unroll
        for (int it = 0; it < 2; it++) {
            const int idx = tid + 256 * it;
            const int r = idx >> 2, c = (idx & 3) * 8;
            cp_async16(&As[r * FA_STR + c], &A[(size_t)(brow + r) * K + k0 + c]);
        }
#pragma unroll
        for (int it = 0; it < 2; it++) {
            const int idx = tid + 256 * it;
            const int r = idx >> 4, c = (idx & 15) * 8;
            cp_async16(&Bs[r * FB_STR + c], &B[(size_t)(k0 + r) * N + bcol + c]);
        }
        asm volatile("cp.async.commit_group;");
    };

    const int KT = K / 32;
    load_stage(0, 0);
    load_stage(1, 32);

    for (int kt = 0; kt < KT; kt++) {
        const int s = kt % 3;
        if (kt + 1 < KT) asm volatile("cp.async.wait_group 1;");
        else             asm volatile("cp.async.wait_group 0;");
        __syncthreads();

        if (kt + 2 < KT) load_stage((kt + 2) % 3, (kt + 2) * 32);

        const __half* As = gsm + s * FSTG;
        const __half* Bs = As + 128 * FA_STR;

#pragma unroll
        for (int ks = 0; ks < 2; ks++) {
            unsigned af[4][4];
#pragma unroll
            for (int mt = 0; mt < 4; mt++)
                ldsm4(af[mt], As + (warp_m + mt * 16 + ldr) * FA_STR + ks * 16 + ldc8);

            unsigned bf[4][2];
#pragma unroll
            for (int nt2 = 0; nt2 < 2; nt2++) {
                unsigned t4[4];
                ldsm4t(t4, Bs + (ks * 16 + ldr) * FB_STR + warp_n + nt2 * 16 + ldc8);
                bf[2 * nt2][0]     = t4[0];
                bf[2 * nt2][1]     = t4[1];
                bf[2 * nt2 + 1][0] = t4[2];
                bf[2 * nt2 + 1][1] = t4[3];
            }

#pragma unroll
            for (int mt = 0; mt < 4; mt++)
#pragma unroll
                for (int nt = 0; nt < 4; nt++)
                    mma_fp16(acc[mt][nt], af[mt], bf[nt][0], bf[nt][1]);
        }
    }

#pragma unroll
    for (int mt = 0; mt < 4; mt++) {
#pragma unroll
        for (int nt = 0; nt < 4; nt++) {
            const int row0 = brow + warp_m + mt * 16 + lr;
            const int col  = bcol + warp_n + nt * 8 + lc * 2;
            const float b0 = bias ? bias[col]     : 0.f;
            const float b1 = bias ? bias[col + 1] : 0.f;
            float2 v0 = make_float2(acc[mt][nt][0] + b0, acc[mt][nt][1] + b1);
            float2 v1 = make_float2(acc[mt][nt][2] + b0, acc[mt][nt][3] + b1);
            *(float2*)&C[(size_t)row0 * N + col]       = v0;
            *(float2*)&C[(size_t)(row0 + 8) * N + col] = v1;
        }
    }
}

// ---------------------------------------------------------------------------
// RoPE + split, one block per row (no in-place update, no sync needed):
// Q -> scaled+roped fp16 hi/lo; K -> roped fp16 hi/lo; V -> single fp16.
// ---------------------------------------------------------------------------
__global__ __launch_bounds__(256)
void rope_split(const float* __restrict__ QKV,
                __half* __restrict__ Qhi, __half* __restrict__ Qlo,
                __half* __restrict__ Khi, __half* __restrict__ Klo,
                __half* __restrict__ Vhi,
                const int* __restrict__ pos_ids)
{
    const int row = blockIdx.x;
    const float* src = QKV + (size_t)row * QKV_N;
    const int pos = pos_ids[row];

    for (int idx = threadIdx.x; idx < QKV_N; idx += 256) {
        const int head = idx >> 7;
        const int d = idx & 127;
        float val = src[idx];

        if (head < NH_ + NKV_) {
            const int i = d & 63;
            const float inv_freq = exp2f(-(float)(2 * i) * (1.0f / 128.0f) * 13.28771238f);
            const float ang = (float)pos * inv_freq;
            float c, s;
            sincosf(ang, &s, &c);
            const float other = (d < 64) ? -src[idx + 64] : src[idx - 64];
            val = val * c + other * s;

            if (head < NH_) {
                val *= 0.08838834764831845f;
                const size_t off = (size_t)row * QN_ + idx;
                const __half h = __float2half_rn(val);
                Qhi[off] = h;
                Qlo[off] = __float2half_rn(val - __half2float(h));
            } else {
                const size_t off = (size_t)row * KN_ + (head - NH_) * HD_ + d;
                const __half h = __float2half_rn(val);
                Khi[off] = h;
                Klo[off] = __float2half_rn(val - __half2float(h));
            }
        } else {
            const size_t off = (size_t)row * KN_ + (head - NH_ - NKV_) * HD_ + d;
            Vhi[off] = __float2half_rn(val);
        }
    }
}

// ---------------------------------------------------------------------------
// Tensor-core flash attention, fp16: QK = 3-MMA (Q,K hi/lo), PV = 1-MMA
// (P fp16, V single fp16). 64 queries/block, 4 warps, 64-key tiles.
// ---------------------------------------------------------------------------
#define BQ 64
#define BK 64
#define KSTR 136
#define ABUF (BK * KSTR * 2)
#define ATT_SMEM (3 * ABUF)          // Khi, Klo, Vhi = 52224 B

__global__ __launch_bounds__(128)
void attn_mma(const __half* __restrict__ Qhi, const __half* __restrict__ Qlo,
              const __half* __restrict__ Khi, const __half* __restrict__ Klo,
              const __half* __restrict__ Vhi,
              __half* __restrict__ AOh)
{
    extern __shared__ char smraw[];
    __half* sKhi = (__half*)(smraw);
    __half* sKlo = (__half*)(smraw + ABUF);
    __half* sVhi = (__half*)(smraw + 2 * ABUF);

    const int qt = blockIdx.x, h = blockIdx.y, b = blockIdx.z;
    const int q0 = qt * BQ;
    const int kvh = h >> 2;
    const int tid = threadIdx.x;
    const int w = tid >> 5, lane = tid & 31;
    const int lr = lane >> 2, lc = lane & 3;

    const int qrow0 = q0 + w * 16 + lr;
    const int qrow1 = qrow0 + 8;

    // Q fragments: direct fp16 hi/lo loads from global
    unsigned qa_hi[8][4], qa_lo[8][4];
    {
        const size_t o0 = ((size_t)(b * S_) + qrow0) * QN_ + h * HD_;
        const size_t o1 = ((size_t)(b * S_) + qrow1) * QN_ + h * HD_;
#pragma unroll
        for (int kt = 0; kt < 8; kt++) {
            const int c0 = kt * 16 + 2 * lc;
            qa_hi[kt][0] = *(const unsigned*)(Qhi + o0 + c0);
            qa_hi[kt][1] = *(const unsigned*)(Qhi + o1 + c0);
            qa_hi[kt][2] = *(const unsigned*)(Qhi + o0 + c0 + 8);
            qa_hi[kt][3] = *(const unsigned*)(Qhi + o1 + c0 + 8);
            qa_lo[kt][0] = *(const unsigned*)(Qlo + o0 + c0);
            qa_lo[kt][1] = *(const unsigned*)(Qlo + o1 + c0);
            qa_lo[kt][2] = *(const unsigned*)(Qlo + o0 + c0 + 8);
            qa_lo[kt][3] = *(const unsigned*)(Qlo + o1 + c0 + 8);
        }
    }

    float m0 = -1e30f, m1 = -1e30f, l0 = 0.f, l1 = 0.f;
    float o[16][4];
#pragma unroll
    for (int i = 0; i < 16; i++)
#pragma unroll
        for (int j = 0; j < 4; j++) o[i][j] = 0.f;

    const int nTiles = qt + 1;
    const int wEnd = q0 + w * 16 + 16;
    const int ldr = (lane & 7) + ((lane >> 3) & 1) * 8;
    const int ldc = ((lane >> 4) & 1) * 8;
    const int klr = lane & 7;
    const int kmg = lane >> 3;

    const size_t kv_base = (size_t)(b * S_) * KN_ + kvh * HD_;

    auto load_k = [&](int kbase) {
        const size_t off = kv_base + (size_t)kbase * KN_;
#pragma unroll
        for (int j = 0; j < 8; j++) {
            const int idx = tid + 128 * j;
            const int row = idx >> 4, c16 = idx & 15;
            const size_t g = off + (size_t)row * KN_ + c16 * 8;
            cp_async16(sKhi + row * KSTR + c16 * 8, Khi + g);
            cp_async16(sKlo + row * KSTR + c16 * 8, Klo + g);
        }
        asm volatile("cp.async.commit_group;");
    };
    auto load_v = [&](int kbase) {
        const size_t off = kv_base + (size_t)kbase * KN_;
#pragma unroll
        for (int j = 0; j < 8; j++) {
            const int idx = tid + 128 * j;
            const int row = idx >> 4, c16 = idx & 15;
            cp_async16(sVhi + row * KSTR + c16 * 8, Vhi + off + (size_t)row * KN_ + c16 * 8);
        }
        asm volatile("cp.async.commit_group;");
    };

    load_k(0);
    asm volatile("cp.async.wait_group 0;");
    __syncthreads();

    for (int kt = 0; kt < nTiles; kt++) {
        const int kbase = kt * BK;
        const bool active = kbase < wEnd;

        load_v(kbase);   // overlaps QK compute

        float sA[8][4];
        unsigned pa[4][4];

        if (active) {
#pragma unroll
            for (int nt = 0; nt < 8; nt++)
#pragma unroll
                for (int j = 0; j < 4; j++) sA[nt][j] = 0.f;

#pragma unroll
            for (int dkt2 = 0; dkt2 < 4; dkt2++) {
                const int col = dkt2 * 32 + kmg * 8;
#pragma unroll
                for (int nt = 0; nt < 8; nt++) {
                    unsigned bh[4], bl[4];
                    ldsm4(bh, sKhi + (nt * 8 + klr) * KSTR + col);
                    ldsm4(bl, sKlo + (nt * 8 + klr) * KSTR + col);
                    mma_fp16(sA[nt], qa_hi[2 * dkt2],     bh[0], bh[1]);
                    mma_fp16(sA[nt], qa_hi[2 * dkt2],     bl[0], bl[1]);
                    mma_fp16(sA[nt], qa_lo[2 * dkt2],     bh[0], bh[1]);
                    mma_fp16(sA[nt], qa_hi[2 * dkt2 + 1], bh[2], bh[3]);
                    mma_fp16(sA[nt], qa_hi[2 * dkt2 + 1], bl[2], bl[3]);
                    mma_fp16(sA[nt], qa_lo[2 * dkt2 + 1], bh[2], bh[3]);
                }
            }

            if (kbase + BK > qrow0) {
#pragma unroll
                for (int nt = 0; nt < 8; nt++) {
                    const int j0 = kbase + nt * 8 + 2 * lc;
                    if (j0 > qrow0)     sA[nt][0] = -1e30f;
                    if (j0 + 1 > qrow0) sA[nt][1] = -1e30f;
                    if (j0 > qrow1)     sA[nt][2] = -1e30f;
                    if (j0 + 1 > qrow1) sA[nt][3] = -1e30f;
                }
            }

            float mt0 = -1e30f, mt1 = -1e30f;
#pragma unroll
            for (int nt = 0; nt < 8; nt++) {
                mt0 = fmaxf(mt0, fmaxf(sA[nt][0], sA[nt][1]));
                mt1 = fmaxf(mt1, fmaxf(sA[nt][2], sA[nt][3]));
            }
            mt0 = fmaxf(mt0, __shfl_xor_sync(0xffffffffu, mt0, 1));
            mt0 = fmaxf(mt0, __shfl_xor_sync(0xffffffffu, mt0, 2));
            mt1 = fmaxf(mt1, __shfl_xor_sync(0xffffffffu, mt1, 1));
            mt1 = fmaxf(mt1, __shfl_xor_sync(0xffffffffu, mt1, 2));

            const float nm0 = fmaxf(m0, mt0);
            const float nm1 = fmaxf(m1, mt1);
            const float al0 = __expf(m0 - nm0);
            const float al1 = __expf(m1 - nm1);

            float rs0 = 0.f, rs1 = 0.f;
#pragma unroll
            for (int nt = 0; nt < 8; nt++) {
                sA[nt][0] = __expf(sA[nt][0] - nm0);
                sA[nt][1] = __expf(sA[nt][1] - nm0);
                sA[nt][2] = __expf(sA[nt][2] - nm1);
                sA[nt][3] = __expf(sA[nt][3] - nm1);
                rs0 += sA[nt][0] + sA[nt][1];
                rs1 += sA[nt][2] + sA[nt][3];
            }
            rs0 += __shfl_xor_sync(0xffffffffu, rs0, 1);
            rs0 += __shfl_xor_sync(0xffffffffu, rs0, 2);
            rs1 += __shfl_xor_sync(0xffffffffu, rs1, 1);
            rs1 += __shfl_xor_sync(0xffffffffu, rs1, 2);

            l0 = l0 * al0 + rs0;
            l1 = l1 * al1 + rs1;
            m0 = nm0; m1 = nm1;

#pragma unroll
            for (int i = 0; i < 16; i++) {
                o[i][0] *= al0; o[i][1] *= al0;
                o[i][2] *= al1; o[i][3] *= al1;
            }

            // P -> single fp16 A-fragments
#pragma unroll
            for (int t = 0; t < 4; t++) {
                __half2 p0 = __floats2half2_rn(sA[2 * t][0],     sA[2 * t][1]);
                __half2 p1 = __floats2half2_rn(sA[2 * t][2],     sA[2 * t][3]);
                __half2 p2 = __floats2half2_rn(sA[2 * t + 1][0], sA[2 * t + 1][1]);
                __half2 p3 = __floats2half2_rn(sA[2 * t + 1][2], sA[2 * t + 1][3]);
                pa[t][0] = *(unsigned*)&p0;
                pa[t][1] = *(unsigned*)&p1;
                pa[t][2] = *(unsigned*)&p2;
                pa[t][3] = *(unsigned*)&p3;
            }
        }

        asm volatile("cp.async.wait_group 0;");
        __syncthreads();

        if (kt + 1 < nTiles) load_k(kbase + BK);   // overlaps PV compute

        if (active) {
#pragma unroll
            for (int t = 0; t < 4; t++) {
#pragma unroll
                for (int np = 0; np < 8; np++) {
                    unsigned vh[4];
                    ldsm4t(vh, sVhi + (t * 16 + ldr) * KSTR + np * 16 + ldc);
                    mma_fp16(o[2 * np],     pa[t], vh[0], vh[1]);
                    mma_fp16(o[2 * np + 1], pa[t], vh[2], vh[3]);
                }
            }
        }

        asm volatile("cp.async.wait_group 0;");
        __syncthreads();
    }

    // epilogue: normalize + fp16 (feeds fp16 O-GEMM)
    const float il0 = 1.f / l0;
    const float il1 = 1.f / l1;
    __half* O0 = AOh + ((size_t)(b * S_) + qrow0) * QN_ + h * HD_;
    __half* O1 = AOh + ((size_t)(b * S_) + qrow1) * QN_ + h * HD_;
#pragma unroll
    for (int nt = 0; nt < 16; nt++) {
        *(__half2*)(O0 + nt * 8 + 2 * lc) =
            __floats2half2_rn(o[nt][0] * il0, o[nt][1] * il0);
        *(__half2*)(O1 + nt * 8 + 2 * lc) =
            __floats2half2_rn(o[nt][2] * il1, o[nt][3] * il1);
    }
}

// ---------------------------------------------------------------------------
// Launcher
// ---------------------------------------------------------------------------
extern "C" void kernel_launch(void* const* d_in, const int* in_sizes, int n_in,
                              void* d_out, int out_size)
{
    const float* X   = (const float*)d_in[0];
    const int*   pos = (const int*)  d_in[1];
    const float* Wq  = (const float*)d_in[2];
    const float* bq  = (const float*)d_in[3];
    const float* Wk  = (const float*)d_in[4];
    const float* bk  = (const float*)d_in[5];
    const float* Wv  = (const float*)d_in[6];
    const float* bv  = (const float*)d_in[7];
    const float* Wo  = (const float*)d_in[8];
    float* out = (float*)d_out;

    __half *Xh, *Wqkvh, *Woh, *AOh, *Qhi, *Qlo, *Khi, *Klo, *Vhi;
    float *bqkv, *QKV;
    cudaGetSymbolAddress((void**)&Xh,    g_Xh);
    cudaGetSymbolAddress((void**)&Wqkvh, g_Wqkvh);
    cudaGetSymbolAddress((void**)&bqkv,  g_bqkv);
    cudaGetSymbolAddress((void**)&QKV,   g_QKV);
    cudaGetSymbolAddress((void**)&Woh,   g_Woh);
    cudaGetSymbolAddress((void**)&AOh,   g_AOh);
    cudaGetSymbolAddress((void**)&Qhi,   g_Qhi);
    cudaGetSymbolAddress((void**)&Qlo,   g_Qlo);
    cudaGetSymbolAddress((void**)&Khi,   g_Khi);
    cudaGetSymbolAddress((void**)&Klo,   g_Klo);
    cudaGetSymbolAddress((void**)&Vhi,   g_Vhi);

    cudaFuncSetAttribute(attn_mma,  cudaFuncAttributeMaxDynamicSharedMemorySize, ATT_SMEM);
    cudaFuncSetAttribute(gemm_fp16, cudaFuncAttributeMaxDynamicSharedMemorySize, G_SMEM);

    // Fused prep (fp16 rounding + concat + bias)
    prep_all<<<1184, 256>>>(X, Wq, Wk, Wv, Wo, bq, bk, bv, Xh, Wqkvh, Woh, bqkv);

    // Fused QKV projection (fp16 tensor cores, fp32 accumulate)
    gemm_fp16<<<dim3(QKV_N / 128, M_ / 128), 256, G_SMEM>>>(
        Xh, Wqkvh, bqkv, QKV, M_, QKV_N, H_);

    // RoPE + splits: Q->hi/lo (scaled), K->hi/lo, V->single fp16
    rope_split<<<M_, 256>>>(QKV, Qhi, Qlo, Khi, Klo, Vhi, pos);

    // Attention (QK 3-MMA, PV 1-MMA), writes fp16 AO
    attn_mma<<<dim3(S_ / BQ, NH_, B_), 128, ATT_SMEM>>>(Qhi, Qlo, Khi, Klo, Vhi, AOh);

    // Output projection (fp16 tensor cores)
    gemm_fp16<<<dim3(QN_ / 128, M_ / 128), 256, G_SMEM>>>(
        AOh, Woh, nullptr, out, M_, QN_, H_);
}

// round 12
// speedup vs baseline: 2.0778x; 1.0382x over previous
#include <cuda_runtime.h>
#include <cuda_bf16.h>
#include <cuda_fp16.h>
#include <math.h>
#include <stdint.h>

// Problem constants
#define B_  2
#define S_  2048
#define H_  4096
#define NH_ 32
#define NKV_ 8
#define HD_ 128
#define M_  (B_ * S_)          // 4096 rows
#define QN_ (NH_ * HD_)        // 4096
#define KN_ (NKV_ * HD_)       // 1024
#define QKV_N (QN_ + 2 * KN_)  // 6144

// Scratch (device globals; no allocations allowed)
__device__ __half g_Xh[M_ * H_];          // fp16-rounded X
__device__ __half g_Wqkvh[H_ * QKV_N];    // concat fp16 weights [H][6144]
__device__ float  g_bqkv[QKV_N];
__device__ __half g_Woh[QN_ * H_];        // fp16 Wo
__device__ __half g_AOh[M_ * QN_];        // attention output (fp16)
__device__ __half g_Qhi[M_ * QN_], g_Qlo[M_ * QN_];   // roped+scaled Q hi/lo
__device__ __half g_Khi[M_ * KN_], g_Klo[M_ * KN_];   // roped K hi/lo
__device__ __half g_Vhi[M_ * KN_];                    // V single fp16

__device__ __forceinline__ void st_half4(__half* p, float4 v)
{
    *(__half2*)(p)     = __floats2half2_rn(v.x, v.y);
    *(__half2*)(p + 2) = __floats2half2_rn(v.z, v.w);
}

// ---------------------------------------------------------------------------
// Fused prep (unchanged)
// ---------------------------------------------------------------------------
#define SEG0 (M_ * H_ / 4)
#define SEG1 (H_ * QKV_N / 4)
#define SEG2 (QN_ * H_ / 4)
#define SEG3 (QKV_N / 4)
#define SEG_TOTAL (SEG0 + SEG1 + SEG2 + SEG3)

__global__ __launch_bounds__(256)
void prep_all(const float* __restrict__ X,
              const float* __restrict__ Wq, const float* __restrict__ Wk,
              const float* __restrict__ Wv, const float* __restrict__ Wo,
              const float* __restrict__ bq, const float* __restrict__ bk,
              const float* __restrict__ bv,
              __half* __restrict__ Xh, __half* __restrict__ Wqkvh,
              __half* __restrict__ Woh, float* __restrict__ bqkv)
{
    const int stride = gridDim.x * 256;
    for (int u = blockIdx.x * 256 + threadIdx.x; u < SEG_TOTAL; u += stride) {
        if (u < SEG0) {
            st_half4(Xh + (size_t)u * 4, *(const float4*)(X + (size_t)u * 4));
        } else if (u < SEG0 + SEG1) {
            const int j = u - SEG0;
            const int row = j / (QKV_N / 4);
            const int c = (j - row * (QKV_N / 4)) * 4;
            float4 v;
            if (c < QN_)
                v = *(const float4*)(Wq + (size_t)row * QN_ + c);
            else if (c < QN_ + KN_)
                v = *(const float4*)(Wk + (size_t)row * KN_ + (c - QN_));
            else
                v = *(const float4*)(Wv + (size_t)row * KN_ + (c - QN_ - KN_));
            st_half4(Wqkvh + (size_t)row * QKV_N + c, v);
        } else if (u < SEG0 + SEG1 + SEG2) {
            const int j = u - SEG0 - SEG1;
            st_half4(Woh + (size_t)j * 4, *(const float4*)(Wo + (size_t)j * 4));
        } else {
            const int j = u - SEG0 - SEG1 - SEG2;
            const int c = j * 4;
            float4 v;
            if (c < QN_)            v = *(const float4*)(bq + c);
            else if (c < QN_ + KN_) v = *(const float4*)(bk + c - QN_);
            else                    v = *(const float4*)(bv + c - QN_ - KN_);
            *(float4*)(bqkv + c) = v;
        }
    }
}

// ---------------------------------------------------------------------------
// Shared MMA / ldmatrix helpers
// ---------------------------------------------------------------------------
__device__ __forceinline__ void cp_async16(void* smem_dst, const void* gsrc) {
    unsigned dst = (unsigned)__cvta_generic_to_shared(smem_dst);
    asm volatile("cp.async.cg.shared.global [%0], [%1], 16;" :: "r"(dst), "l"(gsrc));
}

__device__ __forceinline__ void ldsm4(unsigned r[4], const void* p)
{
    unsigned a = (unsigned)__cvta_generic_to_shared(p);
    asm volatile(
        "ldmatrix.sync.aligned.m8n8.x4.shared.b16 {%0,%1,%2,%3}, [%4];"
        : "=r"(r[0]), "=r"(r[1]), "=r"(r[2]), "=r"(r[3]) : "r"(a));
}

__device__ __forceinline__ void ldsm4t(unsigned r[4], const void* p)
{
    unsigned a = (unsigned)__cvta_generic_to_shared(p);
    asm volatile(
        "ldmatrix.sync.aligned.m8n8.x4.trans.shared.b16 {%0,%1,%2,%3}, [%4];"
        : "=r"(r[0]), "=r"(r[1]), "=r"(r[2]), "=r"(r[3]) : "r"(a));
}

__device__ __forceinline__ void mma_fp16(float c[4], const unsigned a[4],
                                         unsigned b0, unsigned b1)
{
    asm volatile(
        "mma.sync.aligned.m16n8k16.row.col.f32.f16.f16.f32 "
        "{%0,%1,%2,%3}, {%4,%5,%6,%7}, {%8,%9}, {%0,%1,%2,%3};"
        : "+f"(c[0]), "+f"(c[1]), "+f"(c[2]), "+f"(c[3])
        : "r"(a[0]), "r"(a[1]), "r"(a[2]), "r"(a[3]), "r"(b0), "r"(b1));
}

// ---------------------------------------------------------------------------
// GEMM tiling constants (128x128, BK=32, 3-stage)
// ---------------------------------------------------------------------------
#define FA_STR 40
#define FB_STR 136
#define FSTG (128 * FA_STR + 32 * FB_STR)
#define G_SMEM (3 * FSTG * 2)                  // 56832 B (pipeline)
#define TSTR 132
#define QKV_SMEM (128 * TSTR * 4)              // 67584 B (rope tile; >= G_SMEM)

// ---------------------------------------------------------------------------
// Plain FP16 GEMM (O projection): unchanged from R11.
// ---------------------------------------------------------------------------
__global__ __launch_bounds__(256)
void gemm_fp16(const __half* __restrict__ A, const __half* __restrict__ B,
               const float* __restrict__ bias, float* __restrict__ C,
               int M, int N, int K)
{
    extern __shared__ __half gsm[];

    const int tid  = threadIdx.x;
    const int wid  = tid >> 5;
    const int lane = tid & 31;
    const int warp_m = (wid & 1) * 64;
    const int warp_n = (wid >> 1) * 32;
    const int brow = blockIdx.y * 128;
    const int bcol = blockIdx.x * 128;
    const int lr = lane >> 2;
    const int lc = lane & 3;
    const int ldr  = (lane & 7) + ((lane >> 3) & 1) * 8;
    const int ldc8 = ((lane >> 4) & 1) * 8;

    float acc[4][4][4];
#pragma unroll
    for (int mt = 0; mt < 4; mt++)
#pragma unroll
        for (int nt = 0; nt < 4; nt++)
#pragma unroll
            for (int i = 0; i < 4; i++) acc[mt][nt][i] = 0.f;

    auto load_stage = [&](int s, int k0) {
        __half* As = gsm + s * FSTG;
        __half* Bs = As + 128 * FA_STR;
#pragma unroll
        for (int it = 0; it < 2; it++) {
            const int idx = tid + 256 * it;
            const int r = idx >> 2, c = (idx & 3) * 8;
            cp_async16(&As[r * FA_STR + c], &A[(size_t)(brow + r) * K + k0 + c]);
        }
#pragma unroll
        for (int it = 0; it < 2; it++) {
            const int idx = tid + 256 * it;
            const int r = idx >> 4, c = (idx & 15) * 8;
            cp_async16(&Bs[r * FB_STR + c], &B[(size_t)(k0 + r) * N + bcol + c]);
        }
        asm volatile("cp.async.commit_group;");
    };

    const int KT = K / 32;
    load_stage(0, 0);
    load_stage(1, 32);

    for (int kt = 0; kt < KT; kt++) {
        const int s = kt % 3;
        if (kt + 1 < KT) asm volatile("cp.async.wait_group 1;");
        else             asm volatile("cp.async.wait_group 0;");
        __syncthreads();

        if (kt + 2 < KT) load_stage((kt + 2) % 3, (kt + 2) * 32);

        const __half* As = gsm + s * FSTG;
        const __half* Bs = As + 128 * FA_STR;

#pragma unroll
        for (int ks = 0; ks < 2; ks++) {
            unsigned af[4][4];
#pragma unroll
            for (int mt = 0; mt < 4; mt++)
                ldsm4(af[mt], As + (warp_m + mt * 16 + ldr) * FA_STR + ks * 16 + ldc8);

            unsigned bf[4][2];
#pragma unroll
            for (int nt2 = 0; nt2 < 2; nt2++) {
                unsigned t4[4];
                ldsm4t(t4, Bs + (ks * 16 + ldr) * FB_STR + warp_n + nt2 * 16 + ldc8);
                bf[2 * nt2][0]     = t4[0];
                bf[2 * nt2][1]     = t4[1];
                bf[2 * nt2 + 1][0] = t4[2];
                bf[2 * nt2 + 1][1] = t4[3];
            }

#pragma unroll
            for (int mt = 0; mt < 4; mt++)
#pragma unroll
                for (int nt = 0; nt < 4; nt++)
                    mma_fp16(acc[mt][nt], af[mt], bf[nt][0], bf[nt][1]);
        }
    }

#pragma unroll
    for (int mt = 0; mt < 4; mt++) {
#pragma unroll
        for (int nt = 0; nt < 4; nt++) {
            const int row0 = brow + warp_m + mt * 16 + lr;
            const int col  = bcol + warp_n + nt * 8 + lc * 2;
            const float b0 = bias ? bias[col]     : 0.f;
            const float b1 = bias ? bias[col + 1] : 0.f;
            float2 v0 = make_float2(acc[mt][nt][0] + b0, acc[mt][nt][1] + b1);
            float2 v1 = make_float2(acc[mt][nt][2] + b0, acc[mt][nt][3] + b1);
            *(float2*)&C[(size_t)row0 * N + col]       = v0;
            *(float2*)&C[(size_t)(row0 + 8) * N + col] = v1;
        }
    }
}

// ---------------------------------------------------------------------------
// QKV GEMM with fused RoPE epilogue. CTA tile = 128 tokens x 1 head (128 d).
// Mainloop identical to gemm_fp16; epilogue stages acc+bias in smem fp32,
// applies rope (Q: +scale, K) or pass-through (V), writes fp16 hi/lo splits.
// ---------------------------------------------------------------------------
__global__ __launch_bounds__(256)
void gemm_qkv_rope(const __half* __restrict__ A, const __half* __restrict__ B,
                   const float* __restrict__ bias, const int* __restrict__ pos_ids,
                   __half* __restrict__ Qhi, __half* __restrict__ Qlo,
                   __half* __restrict__ Khi, __half* __restrict__ Klo,
                   __half* __restrict__ Vhi)
{
    extern __shared__ __half gsm[];
    const int N = QKV_N, K = H_;

    const int tid  = threadIdx.x;
    const int wid  = tid >> 5;
    const int lane = tid & 31;
    const int warp_m = (wid & 1) * 64;
    const int warp_n = (wid >> 1) * 32;
    const int brow = blockIdx.y * 128;
    const int bcol = blockIdx.x * 128;
    const int lr = lane >> 2;
    const int lc = lane & 3;
    const int ldr  = (lane & 7) + ((lane >> 3) & 1) * 8;
    const int ldc8 = ((lane >> 4) & 1) * 8;

    float acc[4][4][4];
#pragma unroll
    for (int mt = 0; mt < 4; mt++)
#pragma unroll
        for (int nt = 0; nt < 4; nt++)
#pragma unroll
            for (int i = 0; i < 4; i++) acc[mt][nt][i] = 0.f;

    auto load_stage = [&](int s, int k0) {
        __half* As = gsm + s * FSTG;
        __half* Bs = As + 128 * FA_STR;
#pragma unroll
        for (int it = 0; it < 2; it++) {
            const int idx = tid + 256 * it;
            const int r = idx >> 2, c = (idx & 3) * 8;
            cp_async16(&As[r * FA_STR + c], &A[(size_t)(brow + r) * K + k0 + c]);
        }
#pragma unroll
        for (int it = 0; it < 2; it++) {
            const int idx = tid + 256 * it;
            const int r = idx >> 4, c = (idx & 15) * 8;
            cp_async16(&Bs[r * FB_STR + c], &B[(size_t)(k0 + r) * N + bcol + c]);
        }
        asm volatile("cp.async.commit_group;");
    };

    const int KT = K / 32;
    load_stage(0, 0);
    load_stage(1, 32);

    for (int kt = 0; kt < KT; kt++) {
        const int s = kt % 3;
        if (kt + 1 < KT) asm volatile("cp.async.wait_group 1;");
        else             asm volatile("cp.async.wait_group 0;");
        __syncthreads();

        if (kt + 2 < KT) load_stage((kt + 2) % 3, (kt + 2) * 32);

        const __half* As = gsm + s * FSTG;
        const __half* Bs = As + 128 * FA_STR;

#pragma unroll
        for (int ks = 0; ks < 2; ks++) {
            unsigned af[4][4];
#pragma unroll
            for (int mt = 0; mt < 4; mt++)
                ldsm4(af[mt], As + (warp_m + mt * 16 + ldr) * FA_STR + ks * 16 + ldc8);

            unsigned bf[4][2];
#pragma unroll
            for (int nt2 = 0; nt2 < 2; nt2++) {
                unsigned t4[4];
                ldsm4t(t4, Bs + (ks * 16 + ldr) * FB_STR + warp_n + nt2 * 16 + ldc8);
                bf[2 * nt2][0]     = t4[0];
                bf[2 * nt2][1]     = t4[1];
                bf[2 * nt2 + 1][0] = t4[2];
                bf[2 * nt2 + 1][1] = t4[3];
            }

#pragma unroll
            for (int mt = 0; mt < 4; mt++)
#pragma unroll
                for (int nt = 0; nt < 4; nt++)
                    mma_fp16(acc[mt][nt], af[mt], bf[nt][0], bf[nt][1]);
        }
    }

    // ---- epilogue: stage acc+bias in smem fp32, then rope + fp16 split ----
    __syncthreads();                       // all ldsm reads of gsm done
    float* tile = reinterpret_cast<float*>(gsm);

#pragma unroll
    for (int mt = 0; mt < 4; mt++) {
#pragma unroll
        for (int nt = 0; nt < 4; nt++) {
            const int r0 = warp_m + mt * 16 + lr;
            const int c  = warp_n + nt * 8 + lc * 2;
            const float b0 = bias[bcol + c];
            const float b1 = bias[bcol + c + 1];
            tile[r0 * TSTR + c]           = acc[mt][nt][0] + b0;
            tile[r0 * TSTR + c + 1]       = acc[mt][nt][1] + b1;
            tile[(r0 + 8) * TSTR + c]     = acc[mt][nt][2] + b0;
            tile[(r0 + 8) * TSTR + c + 1] = acc[mt][nt][3] + b1;
        }
    }
    __syncthreads();

    const int head = blockIdx.x;           // tile width == HD_

#pragma unroll
    for (int mt = 0; mt < 4; mt++) {
#pragma unroll
        for (int rr = 0; rr < 2; rr++) {
            const int rl = warp_m + mt * 16 + lr + rr * 8;
            const int grow = brow + rl;
            const int pos = pos_ids[grow];

#pragma unroll
            for (int nt = 0; nt < 4; nt++) {
                const int c = warp_n + nt * 8 + lc * 2;
                float v0 = tile[rl * TSTR + c];
                float v1 = tile[rl * TSTR + c + 1];

                if (head < NH_ + NKV_) {
                    // rope: both c, c+1 are on the same side of 64
                    const int poff = (c < 64) ? 64 : -64;
                    const float sgn = (c < 64) ? -1.f : 1.f;
                    const float o0 = sgn * tile[rl * TSTR + c + poff];
                    const float o1 = sgn * tile[rl * TSTR + c + 1 + poff];

                    const int i0 = c & 63, i1 = (c + 1) & 63;
                    float c0, s0, c1, s1;
                    {
                        const float f0 = exp2f(-(float)(2 * i0) * (1.0f / 128.0f) * 13.28771238f);
                        sincosf((float)pos * f0, &s0, &c0);
                        const float f1 = exp2f(-(float)(2 * i1) * (1.0f / 128.0f) * 13.28771238f);
                        sincosf((float)pos * f1, &s1, &c1);
                    }
                    v0 = v0 * c0 + o0 * s0;
                    v1 = v1 * c1 + o1 * s1;

                    if (head < NH_) {
                        v0 *= 0.08838834764831845f;
                        v1 *= 0.08838834764831845f;
                        const size_t off = (size_t)grow * QN_ + head * HD_ + c;
                        __half2 h = __floats2half2_rn(v0, v1);
                        float hx = __low2float(h), hy = __high2float(h);
                        *(__half2*)(Qhi + off) = h;
                        *(__half2*)(Qlo + off) = __floats2half2_rn(v0 - hx, v1 - hy);
                    } else {
                        const size_t off = (size_t)grow * KN_ + (head - NH_) * HD_ + c;
                        __half2 h = __floats2half2_rn(v0, v1);
                        float hx = __low2float(h), hy = __high2float(h);
                        *(__half2*)(Khi + off) = h;
                        *(__half2*)(Klo + off) = __floats2half2_rn(v0 - hx, v1 - hy);
                    }
                } else {
                    const size_t off = (size_t)grow * KN_ + (head - NH_ - NKV_) * HD_ + c;
                    *(__half2*)(Vhi + off) = __floats2half2_rn(v0, v1);
                }
            }
        }
    }
}

// ---------------------------------------------------------------------------
// Tensor-core flash attention (unchanged from R11): QK 3-MMA, PV 1-MMA.
// ---------------------------------------------------------------------------
#define BQ 64
#define BK 64
#define KSTR 136
#define ABUF (BK * KSTR * 2)
#define ATT_SMEM (3 * ABUF)

__global__ __launch_bounds__(128)
void attn_mma(const __half* __restrict__ Qhi, const __half* __restrict__ Qlo,
              const __half* __restrict__ Khi, const __half* __restrict__ Klo,
              const __half* __restrict__ Vhi,
              __half* __restrict__ AOh)
{
    extern __shared__ char smraw[];
    __half* sKhi = (__half*)(smraw);
    __half* sKlo = (__half*)(smraw + ABUF);
    __half* sVhi = (__half*)(smraw + 2 * ABUF);

    const int qt = blockIdx.x, h = blockIdx.y, b = blockIdx.z;
    const int q0 = qt * BQ;
    const int kvh = h >> 2;
    const int tid = threadIdx.x;
    const int w = tid >> 5, lane = tid & 31;
    const int lr = lane >> 2, lc = lane & 3;

    const int qrow0 = q0 + w * 16 + lr;
    const int qrow1 = qrow0 + 8;

    unsigned qa_hi[8][4], qa_lo[8][4];
    {
        const size_t o0 = ((size_t)(b * S_) + qrow0) * QN_ + h * HD_;
        const size_t o1 = ((size_t)(b * S_) + qrow1) * QN_ + h * HD_;
#pragma unroll
        for (int kt = 0; kt < 8; kt++) {
            const int c0 = kt * 16 + 2 * lc;
            qa_hi[kt][0] = *(const unsigned*)(Qhi + o0 + c0);
            qa_hi[kt][1] = *(const unsigned*)(Qhi + o1 + c0);
            qa_hi[kt][2] = *(const unsigned*)(Qhi + o0 + c0 + 8);
            qa_hi[kt][3] = *(const unsigned*)(Qhi + o1 + c0 + 8);
            qa_lo[kt][0] = *(const unsigned*)(Qlo + o0 + c0);
            qa_lo[kt][1] = *(const unsigned*)(Qlo + o1 + c0);
            qa_lo[kt][2] = *(const unsigned*)(Qlo + o0 + c0 + 8);
            qa_lo[kt][3] = *(const unsigned*)(Qlo + o1 + c0 + 8);
        }
    }

    float m0 = -1e30f, m1 = -1e30f, l0 = 0.f, l1 = 0.f;
    float o[16][4];
#pragma unroll
    for (int i = 0; i < 16; i++)
#pragma unroll
        for (int j = 0; j < 4; j++) o[i][j] = 0.f;

    const int nTiles = qt + 1;
    const int wEnd = q0 + w * 16 + 16;
    const int ldr = (lane & 7) + ((lane >> 3) & 1) * 8;
    const int ldc = ((lane >> 4) & 1) * 8;
    const int klr = lane & 7;
    const int kmg = lane >> 3;

    const size_t kv_base = (size_t)(b * S_) * KN_ + kvh * HD_;

    auto load_k = [&](int kbase) {
        const size_t off = kv_base + (size_t)kbase * KN_;
#pragma unroll
        for (int j = 0; j < 8; j++) {
            const int idx = tid + 128 * j;
            const int row = idx >> 4, c16 = idx & 15;
            const size_t g = off + (size_t)row * KN_ + c16 * 8;
            cp_async16(sKhi + row * KSTR + c16 * 8, Khi + g);
            cp_async16(sKlo + row * KSTR + c16 * 8, Klo + g);
        }
        asm volatile("cp.async.commit_group;");
    };
    auto load_v = [&](int kbase) {
        const size_t off = kv_base + (size_t)kbase * KN_;
#pragma unroll
        for (int j = 0; j < 8; j++) {
            const int idx = tid + 128 * j;
            const int row = idx >> 4, c16 = idx & 15;
            cp_async16(sVhi + row * KSTR + c16 * 8, Vhi + off + (size_t)row * KN_ + c16 * 8);
        }
        asm volatile("cp.async.commit_group;");
    };

    load_k(0);
    asm volatile("cp.async.wait_group 0;");
    __syncthreads();

    for (int kt = 0; kt < nTiles; kt++) {
        const int kbase = kt * BK;
        const bool active = kbase < wEnd;

        load_v(kbase);

        float sA[8][4];
        unsigned pa[4][4];

        if (active) {
#pragma unroll
            for (int nt = 0; nt < 8; nt++)
#pragma unroll
                for (int j = 0; j < 4; j++) sA[nt][j] = 0.f;

#pragma unroll
            for (int dkt2 = 0; dkt2 < 4; dkt2++) {
                const int col = dkt2 * 32 + kmg * 8;
#pragma unroll
                for (int nt = 0; nt < 8; nt++) {
                    unsigned bh[4], bl[4];
                    ldsm4(bh, sKhi + (nt * 8 + klr) * KSTR + col);
                    ldsm4(bl, sKlo + (nt * 8 + klr) * KSTR + col);
                    mma_fp16(sA[nt], qa_hi[2 * dkt2],     bh[0], bh[1]);
                    mma_fp16(sA[nt], qa_hi[2 * dkt2],     bl[0], bl[1]);
                    mma_fp16(sA[nt], qa_lo[2 * dkt2],     bh[0], bh[1]);
                    mma_fp16(sA[nt], qa_hi[2 * dkt2 + 1], bh[2], bh[3]);
                    mma_fp16(sA[nt], qa_hi[2 * dkt2 + 1], bl[2], bl[3]);
                    mma_fp16(sA[nt], qa_lo[2 * dkt2 + 1], bh[2], bh[3]);
                }
            }

            if (kbase + BK > qrow0) {
#pragma unroll
                for (int nt = 0; nt < 8; nt++) {
                    const int j0 = kbase + nt * 8 + 2 * lc;
                    if (j0 > qrow0)     sA[nt][0] = -1e30f;
                    if (j0 + 1 > qrow0) sA[nt][1] = -1e30f;
                    if (j0 > qrow1)     sA[nt][2] = -1e30f;
                    if (j0 + 1 > qrow1) sA[nt][3] = -1e30f;
                }
            }

            float mt0 = -1e30f, mt1 = -1e30f;
#pragma unroll
            for (int nt = 0; nt < 8; nt++) {
                mt0 = fmaxf(mt0, fmaxf(sA[nt][0], sA[nt][1]));
                mt1 = fmaxf(mt1, fmaxf(sA[nt][2], sA[nt][3]));
            }
            mt0 = fmaxf(mt0, __shfl_xor_sync(0xffffffffu, mt0, 1));
            mt0 = fmaxf(mt0, __shfl_xor_sync(0xffffffffu, mt0, 2));
            mt1 = fmaxf(mt1, __shfl_xor_sync(0xffffffffu, mt1, 1));
            mt1 = fmaxf(mt1, __shfl_xor_sync(0xffffffffu, mt1, 2));

            const float nm0 = fmaxf(m0, mt0);
            const float nm1 = fmaxf(m1, mt1);
            const float al0 = __expf(m0 - nm0);
            const float al1 = __expf(m1 - nm1);

            float rs0 = 0.f, rs1 = 0.f;
#pragma unroll
            for (int nt = 0; nt < 8; nt++) {
                sA[nt][0] = __expf(sA[nt][0] - nm0);
                sA[nt][1] = __expf(sA[nt][1] - nm0);
                sA[nt][2] = __expf(sA[nt][2] - nm1);
                sA[nt][3] = __expf(sA[nt][3] - nm1);
                rs0 += sA[nt][0] + sA[nt][1];
                rs1 += sA[nt][2] + sA[nt][3];
            }
            rs0 += __shfl_xor_sync(0xffffffffu, rs0, 1);
            rs0 += __shfl_xor_sync(0xffffffffu, rs0, 2);
            rs1 += __shfl_xor_sync(0xffffffffu, rs1, 1);
            rs1 += __shfl_xor_sync(0xffffffffu, rs1, 2);

            l0 = l0 * al0 + rs0;
            l1 = l1 * al1 + rs1;
            m0 = nm0; m1 = nm1;

#pragma unroll
            for (int i = 0; i < 16; i++) {
                o[i][0] *= al0; o[i][1] *= al0;
                o[i][2] *= al1; o[i][3] *= al1;
            }

#pragma unroll
            for (int t = 0; t < 4; t++) {
                __half2 p0 = __floats2half2_rn(sA[2 * t][0],     sA[2 * t][1]);
                __half2 p1 = __floats2half2_rn(sA[2 * t][2],     sA[2 * t][3]);
                __half2 p2 = __floats2half2_rn(sA[2 * t + 1][0], sA[2 * t + 1][1]);
                __half2 p3 = __floats2half2_rn(sA[2 * t + 1][2], sA[2 * t + 1][3]);
                pa[t][0] = *(unsigned*)&p0;
                pa[t][1] = *(unsigned*)&p1;
                pa[t][2] = *(unsigned*)&p2;
                pa[t][3] = *(unsigned*)&p3;
            }
        }

        asm volatile("cp.async.wait_group 0;");
        __syncthreads();

        if (kt + 1 < nTiles) load_k(kbase + BK);

        if (active) {
#pragma unroll
            for (int t = 0; t < 4; t++) {
#pragma unroll
                for (int np = 0; np < 8; np++) {
                    unsigned vh[4];
                    ldsm4t(vh, sVhi + (t * 16 + ldr) * KSTR + np * 16 + ldc);
                    mma_fp16(o[2 * np],     pa[t], vh[0], vh[1]);
                    mma_fp16(o[2 * np + 1], pa[t], vh[2], vh[3]);
                }
            }
        }

        asm volatile("cp.async.wait_group 0;");
        __syncthreads();
    }

    const float il0 = 1.f / l0;
    const float il1 = 1.f / l1;
    __half* O0 = AOh + ((size_t)(b * S_) + qrow0) * QN_ + h * HD_;
    __half* O1 = AOh + ((size_t)(b * S_) + qrow1) * QN_ + h * HD_;
#pragma unroll
    for (int nt = 0; nt < 16; nt++) {
        *(__half2*)(O0 + nt * 8 + 2 * lc) =
            __floats2half2_rn(o[nt][0] * il0, o[nt][1] * il0);
        *(__half2*)(O1 + nt * 8 + 2 * lc) =
            __floats2half2_rn(o[nt][2] * il1, o[nt][3] * il1);
    }
}

// ---------------------------------------------------------------------------
// Launcher
// ---------------------------------------------------------------------------
extern "C" void kernel_launch(void* const* d_in, const int* in_sizes, int n_in,
                              void* d_out, int out_size)
{
    const float* X   = (const float*)d_in[0];
    const int*   pos = (const int*)  d_in[1];
    const float* Wq  = (const float*)d_in[2];
    const float* bq  = (const float*)d_in[3];
    const float* Wk  = (const float*)d_in[4];
    const float* bk  = (const float*)d_in[5];
    const float* Wv  = (const float*)d_in[6];
    const float* bv  = (const float*)d_in[7];
    const float* Wo  = (const float*)d_in[8];
    float* out = (float*)d_out;

    __half *Xh, *Wqkvh, *Woh, *AOh, *Qhi, *Qlo, *Khi, *Klo, *Vhi;
    float *bqkv;
    cudaGetSymbolAddress((void**)&Xh,    g_Xh);
    cudaGetSymbolAddress((void**)&Wqkvh, g_Wqkvh);
    cudaGetSymbolAddress((void**)&bqkv,  g_bqkv);
    cudaGetSymbolAddress((void**)&Woh,   g_Woh);
    cudaGetSymbolAddress((void**)&AOh,   g_AOh);
    cudaGetSymbolAddress((void**)&Qhi,   g_Qhi);
    cudaGetSymbolAddress((void**)&Qlo,   g_Qlo);
    cudaGetSymbolAddress((void**)&Khi,   g_Khi);
    cudaGetSymbolAddress((void**)&Klo,   g_Klo);
    cudaGetSymbolAddress((void**)&Vhi,   g_Vhi);

    cudaFuncSetAttribute(attn_mma,      cudaFuncAttributeMaxDynamicSharedMemorySize, ATT_SMEM);
    cudaFuncSetAttribute(gemm_fp16,     cudaFuncAttributeMaxDynamicSharedMemorySize, G_SMEM);
    cudaFuncSetAttribute(gemm_qkv_rope, cudaFuncAttributeMaxDynamicSharedMemorySize, QKV_SMEM);

    // Fused prep (fp16 rounding + concat + bias)
    prep_all<<<1184, 256>>>(X, Wq, Wk, Wv, Wo, bq, bk, bv, Xh, Wqkvh, Woh, bqkv);

    // Fused QKV projection + RoPE + fp16 splits, all in one kernel
    gemm_qkv_rope<<<dim3(QKV_N / 128, M_ / 128), 256, QKV_SMEM>>>(
        Xh, Wqkvh, bqkv, pos, Qhi, Qlo, Khi, Klo, Vhi);

    // Attention (QK 3-MMA, PV 1-MMA), writes fp16 AO
    attn_mma<<<dim3(S_ / BQ, NH_, B_), 128, ATT_SMEM>>>(Qhi, Qlo, Khi, Klo, Vhi, AOh);

    // Output projection (fp16 tensor cores)
    gemm_fp16<<<dim3(QN_ / 128, M_ / 128), 256, G_SMEM>>>(
        AOh, Woh, nullptr, out, M_, QN_, H_);
}